// round 13
// baseline (speedup 1.0000x reference)
#include <cuda_runtime.h>

typedef unsigned long long ull;

#define FULLMASK 0xffffffffu
#define NB 1024
#define SQ 128
#define K_C   1.2f
#define K_MIN 1e-15f
#define XS 4        // ull stride per k-row (32B)
#define XBW_EH 416  // kEH: 104 rows * XS per warp
#define XBW_K2 512  // k2: 128 rows * XS per warp

__device__ __forceinline__ float kSQC()   { return 1.0954451150103321f; }
__device__ __forceinline__ float kISQC()  { return 0.9128709291752769f; }
__device__ __forceinline__ float kMaxN()  { return 0.90921944545857576f; }
__device__ __forceinline__ float kIMaxN() { return 1.0998446018140677f; }

// packed inter-kernel scratch: token-group g = t0/8; index g*512 + k*4 + p
__device__ ull g_oe2[(NB * SQ / 8) * 512];
__device__ ull g_oh2[(NB * SQ / 8) * 512];
__device__ float g_ohn2[NB * SQ];
__device__ float g_s1[NB * SQ];   // u1.oe + Wte.bae  (per token)
__device__ float g_s2[NB * SQ];   // u2.oe + Wth.bae

// ---------------- packed f32x2 helpers ----------------
__device__ __forceinline__ ull pk2(float a, float b) {
    ull r; asm("mov.b64 %0,{%1,%2};" : "=l"(r) : "f"(a), "f"(b)); return r;
}
__device__ __forceinline__ ull pkd(float a) { return pk2(a, a); }
__device__ __forceinline__ void upk2(ull v, float& a, float& b) {
    asm("mov.b64 {%0,%1},%2;" : "=f"(a), "=f"(b) : "l"(v));
}
__device__ __forceinline__ ull fma2_(ull a, ull b, ull c) {
    ull d; asm("fma.rn.f32x2 %0,%1,%2,%3;" : "=l"(d) : "l"(a), "l"(b), "l"(c)); return d;
}
__device__ __forceinline__ ull add2_(ull a, ull b) {
    ull d; asm("add.rn.f32x2 %0,%1,%2;" : "=l"(d) : "l"(a), "l"(b)); return d;
}
__device__ __forceinline__ ull mul2_(ull a, ull b) {
    ull d; asm("mul.rn.f32x2 %0,%1,%2;" : "=l"(d) : "l"(a), "l"(b)); return d;
}

__device__ __forceinline__ float tanh_a(float x) {   // HW MUFU tanh (sm_75+)
    float y; asm("tanh.approx.f32 %0, %1;" : "=f"(y) : "f"(x)); return y;
}

__device__ __forceinline__ float wsum(float v) {
    v += __shfl_xor_sync(FULLMASK, v, 16);
    v += __shfl_xor_sync(FULLMASK, v, 8);
    v += __shfl_xor_sync(FULLMASK, v, 4);
    v += __shfl_xor_sync(FULLMASK, v, 2);
    v += __shfl_xor_sync(FULLMASK, v, 1);
    return v;
}
__device__ __forceinline__ ull wsum2(ull v) {
    v = add2_(v, __shfl_xor_sync(FULLMASK, v, 16));
    v = add2_(v, __shfl_xor_sync(FULLMASK, v, 8));
    v = add2_(v, __shfl_xor_sync(FULLMASK, v, 4));
    v = add2_(v, __shfl_xor_sync(FULLMASK, v, 2));
    v = add2_(v, __shfl_xor_sync(FULLMASK, v, 1));
    return v;
}

__device__ __forceinline__ float artanh_c(float z) {
    z = fminf(z, 1.0f - 1e-7f);
    return 0.5f * __logf(__fdividef(1.0f + z, 1.0f - z));
}
__device__ __forceinline__ float rnorm_c(float s2) {
    return rsqrtf(fmaxf(s2, 1e-30f));
}

// ------- T8 matvec (smem weights, smem xbuf stride XS) -------
template<int K, int SW, int R>
__device__ __forceinline__ void mvv(const float* __restrict__ Wc,
                                    const ull* __restrict__ xb,
                                    ull (&acc)[R][4]) {
    const int lane = threadIdx.x & 31;
#pragma unroll
    for (int r = 0; r < R; r++)
#pragma unroll
        for (int p = 0; p < 4; p++) acc[r][p] = 0ull;
    const float* wp = Wc + lane * SW;
#pragma unroll 4
    for (int k0 = 0; k0 < K; k0 += 4) {
        float4 wv[R];
#pragma unroll
        for (int r = 0; r < R; r++)
            wv[r] = *(const float4*)(wp + r * 32 * SW + k0);
#pragma unroll
        for (int kk = 0; kk < 4; kk++) {
            const ull* xr = xb + (k0 + kk) * XS;
            ulonglong2 xa = *(const ulonglong2*)(xr);
            ulonglong2 xc = *(const ulonglong2*)(xr + 2);
#pragma unroll
            for (int r = 0; r < R; r++) {
                float w = (kk == 0) ? wv[r].x : (kk == 1) ? wv[r].y
                        : (kk == 2) ? wv[r].z : wv[r].w;
                ull wd = pkd(w);
                acc[r][0] = fma2_(wd, xa.x, acc[r][0]);
                acc[r][1] = fma2_(wd, xa.y, acc[r][1]);
                acc[r][2] = fma2_(wd, xc.x, acc[r][2]);
                acc[r][3] = fma2_(wd, xc.y, acc[r][3]);
            }
        }
    }
}

template<int R>
__device__ __forceinline__ void ssq2(const ull (&v)[R][4], float (&o)[8]) {
#pragma unroll
    for (int p = 0; p < 4; p++) {
        ull a = 0ull;
#pragma unroll
        for (int r = 0; r < R; r++) a = fma2_(v[r][p], v[r][p], a);
        a = wsum2(a);
        upk2(a, o[2 * p], o[2 * p + 1]);
    }
}

template<int R>
__device__ __forceinline__ void scale2(ull (&v)[R][4], const float (&s)[8]) {
    ull sp[4];
#pragma unroll
    for (int p = 0; p < 4; p++) sp[p] = pk2(s[2 * p], s[2 * p + 1]);
#pragma unroll
    for (int r = 0; r < R; r++)
#pragma unroll
        for (int p = 0; p < 4; p++) v[r][p] = mul2_(v[r][p], sp[p]);
}

template<int R>
__device__ __forceinline__ void put2m(ull* xb, const ull (&v)[R][4], int rows) {
    const int lane = threadIdx.x & 31;
#pragma unroll
    for (int r = 0; r < R; r++) {
        int row = lane + 32 * r;
        if (row < rows) {
            ull* d = xb + row * XS;
            ulonglong2 a; a.x = v[r][0]; a.y = v[r][1];
            ulonglong2 c; c.x = v[r][2]; c.y = v[r][3];
            *(ulonglong2*)(d) = a;
            *(ulonglong2*)(d + 2) = c;
        }
    }
}

// expmap0 on packed regs, with analytic out-norm^2 carried
template<int R>
__device__ __forceinline__ void expmap2(ull (&v)[R][4], float (&xn2)[8]) {
    float s2[8];
    ssq2<R>(v, s2);
    float f[8];
#pragma unroll
    for (int t = 0; t < 8; t++) {
        float rn = rnorm_c(s2[t]);
        float n = fmaxf(s2[t], 1e-30f) * rn;
        float tt = tanh_a(kSQC() * n);
        float e = tt * rn * kISQC();
        float ny = tt * kISQC();
        float pg = (ny > kMaxN()) ? __fdividef(kMaxN(), ny) : 1.f;
        f[t] = e * pg;
        ny = fminf(ny, kMaxN());
        xn2[t] = ny * ny;
    }
    scale2<R>(v, f);
}

// p_linear tail: ONE reduction pass (||mv||², <mv,eb>), analytic mobius-add
template<int R>
__device__ __forceinline__ void hyplin_post(const float* __restrict__ eb, float ebn2,
                                            const float (&xn2)[8],
                                            ull (&out)[R][4], float (&on2raw)[8]) {
    const int lane = threadIdx.x & 31;
    float mn2[8], sme[8];
    {
        ull dm[4] = {0ull, 0ull, 0ull, 0ull};
        ull de[4] = {0ull, 0ull, 0ull, 0ull};
#pragma unroll
        for (int r = 0; r < R; r++) {
            ull ed = pkd(eb[lane + 32 * r]);
#pragma unroll
            for (int p = 0; p < 4; p++) {
                dm[p] = fma2_(out[r][p], out[r][p], dm[p]);
                de[p] = fma2_(out[r][p], ed, de[p]);
            }
        }
#pragma unroll
        for (int p = 0; p < 4; p++) {
            ull a = wsum2(dm[p]);
            upk2(a, mn2[2 * p], mn2[2 * p + 1]);
            ull c = wsum2(de[p]);
            upk2(c, sme[2 * p], sme[2 * p + 1]);
        }
    }
    ull A[4], B[4];
#pragma unroll
    for (int p = 0; p < 4; p++) {
        float a0[2], b0[2];
#pragma unroll
        for (int h = 0; h < 2; h++) {
            int t = 2 * p + h;
            float rxn = rnorm_c(xn2[t]);
            float xn = fmaxf(xn2[t], 1e-30f) * rxn;
            float rmn = rnorm_c(mn2[t]);
            float mn = fmaxf(mn2[t], 1e-30f) * rmn;
            float ar = artanh_c(kSQC() * xn);
            float tt = tanh_a(mn * rxn * ar);
            float sc = (mn2[t] == 0.f) ? 0.f : tt * rmn * kISQC();
            float nr = (mn2[t] == 0.f) ? 0.f : tt * kISQC();
            float g = (nr > kMaxN()) ? __fdividef(kMaxN(), nr) : 1.f;
            float tot = sc * g;
            nr = fminf(nr, kMaxN());
            float x2 = nr * nr;
            float xy = tot * sme[t];
            float ca = 1.f + 2.f * K_C * xy + K_C * ebn2;
            float cb = 1.f - K_C * x2;
            float dn = 1.f + 2.f * K_C * xy + K_C * K_C * x2 * ebn2;
            float iv = __fdividef(1.f, fmaxf(dn, K_MIN));
            on2raw[t] = iv * iv * (ca * ca * x2 + 2.f * ca * cb * xy + cb * cb * ebn2);
            a0[h] = ca * tot * iv;
            b0[h] = cb * iv;
        }
        A[p] = pk2(a0[0], a0[1]);
        B[p] = pk2(b0[0], b0[1]);
    }
#pragma unroll
    for (int r = 0; r < R; r++) {
        ull ed = pkd(eb[lane + 32 * r]);
#pragma unroll
        for (int p = 0; p < 4; p++)
            out[r][p] = fma2_(A[p], out[r][p], mul2_(B[p], ed));
    }
}

// Mob_Act(relu)
template<int R>
__device__ __forceinline__ void mobrelu2(ull (&v)[R][4], const float (&on2raw)[8],
                                         float (&xn2n)[8]) {
    float f[8];
#pragma unroll
    for (int t = 0; t < 8; t++) {
        float rn = rnorm_c(on2raw[t]);
        float n = fmaxf(on2raw[t], 1e-30f) * rn;
        float pf, nc, rnc;
        if (n > kMaxN()) { pf = __fdividef(kMaxN(), n); nc = kMaxN(); rnc = kIMaxN(); }
        else             { pf = 1.f; nc = n; rnc = rn; }
        float ls = artanh_c(kSQC() * nc) * rnc * kISQC();
        f[t] = pf * ls;
    }
    ull sp[4] = {0ull, 0ull, 0ull, 0ull};
#pragma unroll
    for (int p = 0; p < 4; p++) {
        ull fp = pk2(f[2 * p], f[2 * p + 1]);
#pragma unroll
        for (int r = 0; r < R; r++) {
            ull w = mul2_(v[r][p], fp);
            float a, b;
            upk2(w, a, b);
            a = fmaxf(a, 0.f);
            b = fmaxf(b, 0.f);
            w = pk2(a, b);
            v[r][p] = w;
            sp[p] = fma2_(w, w, sp[p]);
        }
    }
    float s2[8];
#pragma unroll
    for (int p = 0; p < 4; p++) {
        ull a = wsum2(sp[p]);
        upk2(a, s2[2 * p], s2[2 * p + 1]);
    }
#pragma unroll
    for (int t = 0; t < 8; t++) {
        float rn = rnorm_c(s2[t]);
        float n = fmaxf(s2[t], 1e-30f) * rn;
        float tt = tanh_a(kSQC() * n);
        float e = tt * rn * kISQC();
        float ny = tt * kISQC();
        float pg = (ny > kMaxN()) ? __fdividef(kMaxN(), ny) : 1.f;
        f[t] = e * pg;
        ny = fminf(ny, kMaxN());
        xn2n[t] = ny * ny;
    }
    scale2<R>(v, f);
}

// ---- cooperative smem loaders ----
__device__ __forceinline__ void loadWtCol(float* dst, const float* __restrict__ W,
                                          int J, int K, int Jrows, int SW) {
    int n = Jrows * SW;
    for (int i = threadIdx.x; i < n; i += blockDim.x) {
        int j = i / SW;
        int k = i - j * SW;
        dst[i] = (j < J && k < K) ? W[j * K + k] : 0.f;
    }
}
__device__ __forceinline__ void loadVec(float* dst, const float* __restrict__ v, int J, int Jpad) {
    for (int i = threadIdx.x; i < Jpad; i += blockDim.x) dst[i] = (i < J) ? v[i] : 0.f;
}

template<int R>
__device__ __forceinline__ void expmap_smem(float* v, float* n2out) {
    const int lane = threadIdx.x & 31;
    float a[R];
    float p = 0.f;
#pragma unroll
    for (int r = 0; r < R; r++) {
        a[r] = v[lane + 32 * r];
        p = fmaf(a[r], a[r], p);
    }
    p = wsum(p);
    float n = fmaxf(sqrtf(p), K_MIN);
    float tt = tanhf(fminf(kSQC() * n, 15.f));
    float scv = tt / (kSQC() * n);
#pragma unroll
    for (int r = 0; r < R; r++) a[r] *= scv;
    float q = 0.f;
#pragma unroll
    for (int r = 0; r < R; r++) q = fmaf(a[r], a[r], q);
    q = wsum(q);
    float nn = fmaxf(sqrtf(q), K_MIN);
    if (nn > kMaxN()) {
        float fsc = kMaxN() / nn;
#pragma unroll
        for (int r = 0; r < R; r++) a[r] *= fsc;
    }
    float y2 = 0.f;
#pragma unroll
    for (int r = 0; r < R; r++) y2 = fmaf(a[r], a[r], y2);
    y2 = wsum(y2);
#pragma unroll
    for (int r = 0; r < R; r++) v[lane + 32 * r] = a[r];
    if (lane == 0) *n2out = y2;
}

extern __shared__ float sm[];

// ===== Fused kernel EH: even blocks = Euclid path, odd blocks = hyperbolic ====
#define EH_B1 13824
#define EH_B2 13920
#define EH_B3 14048
#define EH_N2 14176
#define EH_U1 14180
#define EH_U2 14308
#define EH_XOFF 14436
__global__ void __launch_bounds__(512, 2) kEH_kernel(
    const float* __restrict__ x,
    const float* __restrict__ We1, const float* __restrict__ be1,
    const float* __restrict__ We2, const float* __restrict__ be2,
    const float* __restrict__ We3, const float* __restrict__ be3,
    const float* __restrict__ Wh1, const float* __restrict__ bh1,
    const float* __restrict__ Wh2, const float* __restrict__ bh2,
    const float* __restrict__ Wh3, const float* __restrict__ bh3,
    const float* __restrict__ Wae, const float* __restrict__ bae,
    const float* __restrict__ Wte, const float* __restrict__ Wth) {
    const int lane = threadIdx.x & 31;
    const int warp = threadIdx.x >> 5;
    const int isH = blockIdx.x & 1;
    const int b = blockIdx.x >> 1;
    const int t0 = b * 128 + warp * 8;
    const int grp = t0 >> 3;
    ull* xb = (ull*)(sm + EH_XOFF) + warp * XBW_EH;

    if (!isH) {
        // ---- E-path prologue: in-block u1/u2/c1/c2 + bias/weight loads ----
        loadVec(sm + EH_U1, Wte, 128, 128);   // temporarily Wte
        loadVec(sm + EH_U2, Wth, 128, 128);   // temporarily Wth
        float* tbae = sm + EH_XOFF;           // xbuf scratch, safe until sync
        loadVec(tbae, bae, 128, 128);
        loadVec(sm + EH_B1, be1, 80, 96);
        loadVec(sm + EH_B2, be2, 104, 128);
        loadVec(sm + EH_B3, be3, 128, 128);
        loadWtCol(sm, We1, 80, 32, 96, 36);
        __syncthreads();
        const int tt = threadIdx.x >> 2, qq = threadIdx.x & 3;
        float p1 = 0.f, p2 = 0.f;
#pragma unroll 8
        for (int jj = 0; jj < 32; jj++) {
            int j = qq * 32 + jj;
            float w = Wae[j * 128 + tt];
            p1 = fmaf(w, sm[EH_U1 + j], p1);
            p2 = fmaf(w, sm[EH_U2 + j], p2);
        }
        p1 += __shfl_down_sync(FULLMASK, p1, 1);
        p1 += __shfl_down_sync(FULLMASK, p1, 2);
        p2 += __shfl_down_sync(FULLMASK, p2, 1);
        p2 += __shfl_down_sync(FULLMASK, p2, 2);
        float c1v = 0.f, c2v = 0.f;
        if (warp == 0) {
            float a = 0.f, c = 0.f;
#pragma unroll
            for (int jj = 0; jj < 4; jj++) {
                int j = lane + 32 * jj;
                a = fmaf(sm[EH_U1 + j], tbae[j], a);
                c = fmaf(sm[EH_U2 + j], tbae[j], c);
            }
            c1v = wsum(a);
            c2v = wsum(c);
        }
        __syncthreads();   // all reads of Wte/Wth/bae done
        if (qq == 0) { sm[EH_U1 + tt] = p1; sm[EH_U2 + tt] = p2; }
        if (warp == 0 && lane == 0) { sm[EH_N2 + 0] = c1v; sm[EH_N2 + 1] = c2v; }
        __syncthreads();

        {
            const int bb = t0 >> 7, s0 = t0 & 127;
            const float* xsrc = x + bb * (32 * 128) + lane * 128 + s0;
            float4 a0 = *(const float4*)(xsrc);
            float4 a1 = *(const float4*)(xsrc + 4);
            ull* d = xb + lane * XS;
            ulonglong2 u0; u0.x = pk2(a0.x, a0.y); u0.y = pk2(a0.z, a0.w);
            ulonglong2 u1; u1.x = pk2(a1.x, a1.y); u1.y = pk2(a1.z, a1.w);
            *(ulonglong2*)(d) = u0;
            *(ulonglong2*)(d + 2) = u1;
        }
        __syncwarp();

        ull h1[3][4];
        mvv<32, 36, 3>(sm, xb, h1);
#pragma unroll
        for (int r = 0; r < 3; r++) {
            float bv = sm[EH_B1 + lane + 32 * r];
#pragma unroll
            for (int p = 0; p < 4; p++) {
                float a, c;
                upk2(h1[r][p], a, c);
                h1[r][p] = pk2(fmaxf(a + bv, 0.f), fmaxf(c + bv, 0.f));
            }
        }
        put2m<3>(xb, h1, 104);
        __syncthreads();
        loadWtCol(sm, We2, 104, 80, 128, 84);
        __syncthreads();

        ull h2[4][4];
        mvv<80, 84, 4>(sm, xb, h2);
#pragma unroll
        for (int r = 0; r < 4; r++) {
            float bv = sm[EH_B2 + lane + 32 * r];
#pragma unroll
            for (int p = 0; p < 4; p++) {
                float a, c;
                upk2(h2[r][p], a, c);
                h2[r][p] = pk2(fmaxf(a + bv, 0.f), fmaxf(c + bv, 0.f));
            }
        }
        put2m<4>(xb, h2, 104);
        __syncthreads();
        loadWtCol(sm, We3, 128, 104, 128, 108);
        __syncthreads();

        ull h3[4][4];
        mvv<104, 108, 4>(sm, xb, h3);
        ull d1[4] = {0ull, 0ull, 0ull, 0ull};
        ull d2[4] = {0ull, 0ull, 0ull, 0ull};
        ull* dst = g_oe2 + (size_t)grp * 512;
#pragma unroll
        for (int r = 0; r < 4; r++) {
            int k = lane + 32 * r;
            float bv = sm[EH_B3 + k];
            ull w1d = pkd(sm[EH_U1 + k]);
            ull w2d = pkd(sm[EH_U2 + k]);
            ull vP[4];
#pragma unroll
            for (int p = 0; p < 4; p++) {
                float a, c;
                upk2(h3[r][p], a, c);
                ull v = pk2(fmaxf(a + bv, 0.f), fmaxf(c + bv, 0.f));
                vP[p] = v;
                d1[p] = fma2_(w1d, v, d1[p]);
                d2[p] = fma2_(w2d, v, d2[p]);
            }
            ull* dr = dst + k * 4;
            ulonglong2 u;
            u.x = vP[0]; u.y = vP[1];
            *(ulonglong2*)(dr) = u;
            u.x = vP[2]; u.y = vP[3];
            *(ulonglong2*)(dr + 2) = u;
        }
        const float c1 = sm[EH_N2 + 0], c2 = sm[EH_N2 + 1];
        float s1v[8], s2v[8];
#pragma unroll
        for (int p = 0; p < 4; p++) {
            ull a = wsum2(d1[p]);
            upk2(a, s1v[2 * p], s1v[2 * p + 1]);
            ull c = wsum2(d2[p]);
            upk2(c, s2v[2 * p], s2v[2 * p + 1]);
        }
#pragma unroll
        for (int t = 0; t < 8; t++)
            if (lane == t) {
                g_s1[t0 + t] = s1v[t] + c1;
                g_s2[t0 + t] = s2v[t] + c2;
            }
    } else {
        loadVec(sm + EH_B1, bh1, 80, 96);
        loadVec(sm + EH_B2, bh2, 104, 128);
        loadVec(sm + EH_B3, bh3, 128, 128);
        loadWtCol(sm, Wh1, 80, 32, 96, 36);
        __syncthreads();
        if (warp == 0) expmap_smem<3>(sm + EH_B1, sm + EH_N2 + 0);
        else if (warp == 1) expmap_smem<4>(sm + EH_B2, sm + EH_N2 + 1);
        else if (warp == 2) expmap_smem<4>(sm + EH_B3, sm + EH_N2 + 2);
        __syncthreads();
        const float e1n2 = sm[EH_N2 + 0], e2n2 = sm[EH_N2 + 1], e3n2 = sm[EH_N2 + 2];

        ull xh[1][4];
        {
            const int bb = t0 >> 7, s0 = t0 & 127;
            const float* xsrc = x + bb * (32 * 128) + lane * 128 + s0;
            float4 a0 = *(const float4*)(xsrc);
            float4 a1 = *(const float4*)(xsrc + 4);
            xh[0][0] = pk2(a0.x, a0.y);
            xh[0][1] = pk2(a0.z, a0.w);
            xh[0][2] = pk2(a1.x, a1.y);
            xh[0][3] = pk2(a1.z, a1.w);
        }
        float xn2[8];
        expmap2<1>(xh, xn2);
        __syncwarp();
        put2m<1>(xb, xh, 104);
        __syncwarp();

        ull y1[3][4];
        float on2[8];
        mvv<32, 36, 3>(sm, xb, y1);
        hyplin_post<3>(sm + EH_B1, e1n2, xn2, y1, on2);
        mobrelu2<3>(y1, on2, xn2);
        put2m<3>(xb, y1, 104);
        __syncthreads();
        loadWtCol(sm, Wh2, 104, 80, 128, 84);
        __syncthreads();

        ull y2[4][4];
        mvv<80, 84, 4>(sm, xb, y2);
        hyplin_post<4>(sm + EH_B2, e2n2, xn2, y2, on2);
        mobrelu2<4>(y2, on2, xn2);
        put2m<4>(xb, y2, 104);
        __syncthreads();
        loadWtCol(sm, Wh3, 128, 104, 128, 108);
        __syncthreads();

        ull y3[4][4];
        mvv<104, 108, 4>(sm, xb, y3);
        hyplin_post<4>(sm + EH_B3, e3n2, xn2, y3, on2);
        float pf[8], nn[8];
#pragma unroll
        for (int t = 0; t < 8; t++) {
            float rn = rnorm_c(on2[t]);
            float n = fmaxf(on2[t], 1e-30f) * rn;
            pf[t] = (n > kMaxN()) ? __fdividef(kMaxN(), n) : 1.f;
            float nc = fminf(n, kMaxN());
            nn[t] = nc * nc;
        }
        ull pf2[4];
#pragma unroll
        for (int p = 0; p < 4; p++) pf2[p] = pk2(pf[2 * p], pf[2 * p + 1]);
        ull* dst = g_oh2 + (size_t)grp * 512;
#pragma unroll
        for (int r = 0; r < 4; r++) {
            ull* dr = dst + (lane + 32 * r) * 4;
            ulonglong2 u;
            u.x = mul2_(y3[r][0], pf2[0]);
            u.y = mul2_(y3[r][1], pf2[1]);
            *(ulonglong2*)(dr) = u;
            u.x = mul2_(y3[r][2], pf2[2]);
            u.y = mul2_(y3[r][3], pf2[3]);
            *(ulonglong2*)(dr + 2) = u;
        }
#pragma unroll
        for (int t = 0; t < 8; t++)
            if (lane == t) g_ohn2[t0 + t] = nn[t];
    }
}

// ==== Kernel 2: mv matvec + single reduction; linear scalars via Wah^T pullback
#define K2_W   0
#define K2_V1  16896
#define K2_V2  17024
#define K2_V3  17152
#define K2_EBT 17280
#define K2_SCA 17408
#define K2_OS  17412
#define K2_HS  17668
#define K2_XOFF 17684
__global__ void __launch_bounds__(512) k2_kernel(
    const float* __restrict__ Wah, const float* __restrict__ bah,
    const float* __restrict__ Wte, const float* __restrict__ bte,
    const float* __restrict__ Wth, const float* __restrict__ bth,
    const float* __restrict__ Wf1, const float* __restrict__ bf1,
    const float* __restrict__ Wf2, const float* __restrict__ bf2,
    float* __restrict__ out) {
    const int warp = threadIdx.x >> 5;
    const int lane = threadIdx.x & 31;
    float* twte = sm + K2_XOFF;          // xbuf scratch (pre-staging)
    float* twth = twte + 128;
    loadWtCol(sm + K2_W, Wah, 128, 128, 128, 132);
    loadVec(sm + K2_EBT, bah, 128, 128);
    loadVec(twte, Wte, 128, 128);
    loadVec(twth, Wth, 128, 128);
    __syncthreads();
    if (warp == 0) expmap_smem<4>(sm + K2_EBT, sm + K2_SCA);   // eb, ebn2
    __syncthreads();
    // v1 = Wah^T eb, v2 = Wah^T Wte, v3 = Wah^T Wth (column sums of smem slab)
    {
        const int kk2 = threadIdx.x >> 2, qq = threadIdx.x & 3;
        float v1a = 0.f, v2a = 0.f, v3a = 0.f;
#pragma unroll 8
        for (int jj = 0; jj < 32; jj++) {
            int j = qq * 32 + jj;
            float w = sm[K2_W + j * 132 + kk2];
            v1a = fmaf(w, sm[K2_EBT + j], v1a);
            v2a = fmaf(w, twte[j], v2a);
            v3a = fmaf(w, twth[j], v3a);
        }
        v1a += __shfl_down_sync(FULLMASK, v1a, 1);
        v1a += __shfl_down_sync(FULLMASK, v1a, 2);
        v2a += __shfl_down_sync(FULLMASK, v2a, 1);
        v2a += __shfl_down_sync(FULLMASK, v2a, 2);
        v3a += __shfl_down_sync(FULLMASK, v3a, 1);
        v3a += __shfl_down_sync(FULLMASK, v3a, 2);
        float aeb = 0.f, ceb = 0.f;
        if (warp == 0) {
#pragma unroll
            for (int jj = 0; jj < 4; jj++) {
                int j = lane + 32 * jj;
                aeb = fmaf(twte[j], sm[K2_EBT + j], aeb);
                ceb = fmaf(twth[j], sm[K2_EBT + j], ceb);
            }
            aeb = wsum(aeb);
            ceb = wsum(ceb);
        }
        __syncthreads();   // reads of twte/twth done before xbuf staging
        if (qq == 0) {
            sm[K2_V1 + kk2] = v1a;
            sm[K2_V2 + kk2] = v2a;
            sm[K2_V3 + kk2] = v3a;
        }
        if (warp == 0 && lane == 0) { sm[K2_SCA + 1] = aeb; sm[K2_SCA + 2] = ceb; }
        __syncthreads();
    }
    const float ebn2 = sm[K2_SCA];
    const float wteeb = sm[K2_SCA + 1], wtheb = sm[K2_SCA + 2];
    const float bte0 = bte[0], bth0 = bth[0];
    const int t0 = blockIdx.x * 128 + warp * 8;
    const int grp = t0 >> 3;
    ull* xb = (ull*)(sm + K2_XOFF) + warp * XBW_K2;

    // ---- stage oh to xbuf; fused dot products <oh,v1>,<oh,v2>,<oh,v3> ----
    float sme[8], smt[8], smh[8];
    {
        const ull* src = g_oh2 + (size_t)grp * 512;
        ull de[4] = {0ull, 0ull, 0ull, 0ull};
        ull dt[4] = {0ull, 0ull, 0ull, 0ull};
        ull dh[4] = {0ull, 0ull, 0ull, 0ull};
#pragma unroll
        for (int r = 0; r < 4; r++) {
            int k = lane + 32 * r;
            ulonglong2 u0 = *(const ulonglong2*)(src + k * 4);
            ulonglong2 u1v = *(const ulonglong2*)(src + k * 4 + 2);
            ull* d = xb + k * XS;
            *(ulonglong2*)(d) = u0;
            *(ulonglong2*)(d + 2) = u1v;
            ull p1 = pkd(sm[K2_V1 + k]);
            ull p2 = pkd(sm[K2_V2 + k]);
            ull p3 = pkd(sm[K2_V3 + k]);
            de[0] = fma2_(p1, u0.x, de[0]); de[1] = fma2_(p1, u0.y, de[1]);
            de[2] = fma2_(p1, u1v.x, de[2]); de[3] = fma2_(p1, u1v.y, de[3]);
            dt[0] = fma2_(p2, u0.x, dt[0]); dt[1] = fma2_(p2, u0.y, dt[1]);
            dt[2] = fma2_(p2, u1v.x, dt[2]); dt[3] = fma2_(p2, u1v.y, dt[3]);
            dh[0] = fma2_(p3, u0.x, dh[0]); dh[1] = fma2_(p3, u0.y, dh[1]);
            dh[2] = fma2_(p3, u1v.x, dh[2]); dh[3] = fma2_(p3, u1v.y, dh[3]);
        }
#pragma unroll
        for (int p = 0; p < 4; p++) {
            ull c = wsum2(de[p]); upk2(c, sme[2 * p], sme[2 * p + 1]);
            ull e = wsum2(dt[p]); upk2(e, smt[2 * p], smt[2 * p + 1]);
            ull g = wsum2(dh[p]); upk2(g, smh[2 * p], smh[2 * p + 1]);
        }
    }
    float xn2[8];
#pragma unroll
    for (int t = 0; t < 8; t++) xn2[t] = g_ohn2[t0 + t];
    __syncwarp();

    ull m[4][4];
    mvv<128, 132, 4>(sm + K2_W, xb, m);

    // ---- single-stream reduction: ||mv||² ----
    float mn2[8];
    ssq2<4>(m, mn2);

    // ---- per-token scalars ----
    float w0[8], w1[8];
#pragma unroll
    for (int t = 0; t < 8; t++) {
        float rxn = rnorm_c(xn2[t]);
        float xn = fmaxf(xn2[t], 1e-30f) * rxn;
        float rmn = rnorm_c(mn2[t]);
        float mn = fmaxf(mn2[t], 1e-30f) * rmn;
        float ar = artanh_c(kSQC() * xn);
        float tth = tanh_a(mn * rxn * ar);
        float scv = (mn2[t] == 0.f) ? 0.f : tth * rmn * kISQC();
        float nr = (mn2[t] == 0.f) ? 0.f : tth * kISQC();
        float g = (nr > kMaxN()) ? __fdividef(kMaxN(), nr) : 1.f;
        float tot = scv * g;
        nr = fminf(nr, kMaxN());
        float x2 = nr * nr;
        float xy = tot * sme[t];
        float ca = 1.f + 2.f * K_C * xy + K_C * ebn2;
        float cb = 1.f - K_C * x2;
        float dn = 1.f + 2.f * K_C * xy + K_C * K_C * x2 * ebn2;
        float iv = __fdividef(1.f, fmaxf(dn, K_MIN));
        float on2 = iv * iv * (ca * ca * x2 + 2.f * ca * cb * xy + cb * cb * ebn2);
        float Af = ca * tot * iv;
        float Bf = cb * iv;
        float rn = rnorm_c(on2);
        float n = fmaxf(on2, 1e-30f) * rn;
        float pf, nc, rnc;
        if (n > kMaxN()) { pf = __fdividef(kMaxN(), n); nc = kMaxN(); rnc = kIMaxN(); }
        else             { pf = 1.f; nc = n; rnc = rn; }
        float f = pf * (artanh_c(kSQC() * nc) * rnc * kISQC());
        float s3 = f * (Af * smt[t] + Bf * wteeb);   // Wte . th
        float s4 = f * (Af * smh[t] + Bf * wtheb);   // Wth . th
        float aet = 0.5f * (g_s1[t0 + t] - s3) + bte0;
        float aht = 0.5f * (s4 - g_s2[t0 + t]) + bth0;
        float mx = fmaxf(aet, aht);
        float e0 = __expf(aet - mx), e1 = __expf(aht - mx);
        float inv = __fdividef(1.f, e0 + e1);
        w0[t] = e0 * inv;
        w1[t] = e1 * inv;
    }

    // ---- proc_e = w0 * out_e (stream from g_oe2), pool ----
    float acce[4];
    {
        const ull* pe = g_oe2 + (size_t)grp * 512;
        ull w0p[4];
#pragma unroll
        for (int p = 0; p < 4; p++) w0p[p] = pk2(w0[2 * p], w0[2 * p + 1]);
#pragma unroll
        for (int r = 0; r < 4; r++) {
            int k = lane + 32 * r;
            ulonglong2 u0 = *(const ulonglong2*)(pe + k * 4);
            ulonglong2 u1v = *(const ulonglong2*)(pe + k * 4 + 2);
            ull a = mul2_(w0p[0], u0.x);
            a = fma2_(w0p[1], u0.y, a);
            a = fma2_(w0p[2], u1v.x, a);
            a = fma2_(w0p[3], u1v.y, a);
            float x0, x1;
            upk2(a, x0, x1);
            acce[r] = x0 + x1;
        }
    }

    // ---- proc_h = logmap0(projx(mobius_scalar_mul(w1, out_h))), pool ----
    float acch[4];
    {
        float tt[8];
#pragma unroll
        for (int t = 0; t < 8; t++) {
            float rn = rnorm_c(xn2[t]);
            float n = fmaxf(xn2[t], 1e-30f) * rn;
            float ar = artanh_c(kSQC() * n);
            float q = tanh_a(w1[t] * ar);
            float scv = q * rn * kISQC();
            float qn = q * kISQC();
            float pg = (qn > kMaxN()) ? __fdividef(kMaxN(), qn) : 1.f;
            float qc = fmaxf(fminf(qn, kMaxN()), K_MIN);
            float ls = artanh_c(kSQC() * qc) * __fdividef(1.f, kSQC() * qc);
            tt[t] = scv * pg * ls;
        }
        ull tp[4];
#pragma unroll
        for (int p = 0; p < 4; p++) tp[p] = pk2(tt[2 * p], tt[2 * p + 1]);
#pragma unroll
        for (int r = 0; r < 4; r++) {
            const ull* d = xb + (lane + 32 * r) * XS;
            ulonglong2 u0 = *(const ulonglong2*)(d);
            ulonglong2 u1v = *(const ulonglong2*)(d + 2);
            ull a = mul2_(tp[0], u0.x);
            a = fma2_(tp[1], u0.y, a);
            a = fma2_(tp[2], u1v.x, a);
            a = fma2_(tp[3], u1v.y, a);
            float x0, x1;
            upk2(a, x0, x1);
            acch[r] = x0 + x1;
        }
    }

    float* pes = sm + K2_XOFF;          // dead xbuf reuse
    float* phs = pes + 2048;
    __syncthreads();
#pragma unroll
    for (int r = 0; r < 4; r++) {
        pes[warp * 128 + lane + 32 * r] = acce[r];
        phs[warp * 128 + lane + 32 * r] = acch[r];
    }
    __syncthreads();

    float* os = sm + K2_OS;
    float* hs = sm + K2_HS;
    for (int j = threadIdx.x; j < 256; j += 512) {
        const float* src = (j < 128) ? (pes + j) : (phs + (j - 128));
        float s = 0.f;
#pragma unroll
        for (int i = 0; i < 16; i++) s += src[i * 128];
        os[j] = s * (1.0f / 128.0f);
    }
    __syncthreads();

    if (threadIdx.x < 32) {
        if (lane < 10) {
            float h = bf1[lane];
            for (int i = 0; i < 256; i++) h = fmaf(Wf1[lane * 256 + i], os[i], h);
            hs[lane] = fmaxf(h, 0.f);
        }
        __syncwarp();
        if (lane < 10) {
            float o2 = bf2[lane];
#pragma unroll
            for (int i = 0; i < 10; i++) o2 = fmaf(Wf2[lane * 10 + i], hs[i], o2);
            out[blockIdx.x * 10 + lane] = o2;
        }
    }
}

extern "C" void kernel_launch(void* const* d_in, const int* in_sizes, int n_in,
                              void* d_out, int out_size) {
    (void)in_sizes; (void)n_in; (void)out_size;
    const float* x   = (const float*)d_in[0];
    const float* We1 = (const float*)d_in[1];  const float* be1 = (const float*)d_in[2];
    const float* We2 = (const float*)d_in[3];  const float* be2 = (const float*)d_in[4];
    const float* We3 = (const float*)d_in[5];  const float* be3 = (const float*)d_in[6];
    const float* Wh1 = (const float*)d_in[7];  const float* bh1 = (const float*)d_in[8];
    const float* Wh2 = (const float*)d_in[9];  const float* bh2 = (const float*)d_in[10];
    const float* Wh3 = (const float*)d_in[11]; const float* bh3 = (const float*)d_in[12];
    const float* Wae = (const float*)d_in[13]; const float* bae = (const float*)d_in[14];
    const float* Wah = (const float*)d_in[15]; const float* bah = (const float*)d_in[16];
    const float* Wte = (const float*)d_in[17]; const float* bte = (const float*)d_in[18];
    const float* Wth = (const float*)d_in[19]; const float* bth = (const float*)d_in[20];
    const float* Wf1 = (const float*)d_in[21]; const float* bf1 = (const float*)d_in[22];
    const float* Wf2 = (const float*)d_in[23]; const float* bf2 = (const float*)d_in[24];
    float* out = (float*)d_out;

    size_t smEH = (size_t)(EH_XOFF + 16 * XBW_EH * 2) * sizeof(float);  // ~111 KB
    size_t sm2  = (size_t)(K2_XOFF + 16 * XBW_K2 * 2) * sizeof(float);  // ~136 KB

    cudaFuncSetAttribute(kEH_kernel, cudaFuncAttributeMaxDynamicSharedMemorySize, (int)smEH);
    cudaFuncSetAttribute(k2_kernel, cudaFuncAttributeMaxDynamicSharedMemorySize, (int)sm2);

    kEH_kernel<<<2 * NB, 512, smEH>>>(x, We1, be1, We2, be2, We3, be3,
                                      Wh1, bh1, Wh2, bh2, Wh3, bh3,
                                      Wae, bae, Wte, Wth);
    k2_kernel<<<NB, 512, sm2>>>(Wah, bah, Wte, bte, Wth, bth,
                                Wf1, bf1, Wf2, bf2, out);
}

// round 14
// speedup vs baseline: 1.0715x; 1.0715x over previous
#include <cuda_runtime.h>

typedef unsigned long long ull;

#define FULLMASK 0xffffffffu
#define NB 1024
#define SQ 128
#define K_C   1.2f
#define K_MIN 1e-15f
#define XS 4        // ull stride per k-row (32B)
#define XBW_EH 416  // kEH: 104 rows * XS per warp
#define XBW_K2 512  // k2: 128 rows * XS per warp

__device__ __forceinline__ float kSQC()   { return 1.0954451150103321f; }
__device__ __forceinline__ float kISQC()  { return 0.9128709291752769f; }
__device__ __forceinline__ float kMaxN()  { return 0.90921944545857576f; }
__device__ __forceinline__ float kIMaxN() { return 1.0998446018140677f; }

// packed inter-kernel scratch: token-group g = t0/8; index g*512 + k*4 + p
__device__ ull g_oe2[(NB * SQ / 8) * 512];
__device__ ull g_oh2[(NB * SQ / 8) * 512];
__device__ float g_ohn2[NB * SQ];
__device__ float g_s1[NB * SQ];   // u1.oe + Wte.bae  (per token)
__device__ float g_s2[NB * SQ];   // u2.oe + Wth.bae
// prologue-precomputed attention algebra
__device__ float g_u1[128];   // Wae^T * Wte
__device__ float g_u2[128];   // Wae^T * Wth
__device__ float g_eb[128];   // expmap0(bah)
__device__ float g_pre[8];    // [0]=ebn2 [1]=Wte.bae [2]=Wth.bae [3]=Wte.eb [4]=Wth.eb

// ---------------- packed f32x2 helpers ----------------
__device__ __forceinline__ ull pk2(float a, float b) {
    ull r; asm("mov.b64 %0,{%1,%2};" : "=l"(r) : "f"(a), "f"(b)); return r;
}
__device__ __forceinline__ ull pkd(float a) { return pk2(a, a); }
__device__ __forceinline__ void upk2(ull v, float& a, float& b) {
    asm("mov.b64 {%0,%1},%2;" : "=f"(a), "=f"(b) : "l"(v));
}
__device__ __forceinline__ ull fma2_(ull a, ull b, ull c) {
    ull d; asm("fma.rn.f32x2 %0,%1,%2,%3;" : "=l"(d) : "l"(a), "l"(b), "l"(c)); return d;
}
__device__ __forceinline__ ull add2_(ull a, ull b) {
    ull d; asm("add.rn.f32x2 %0,%1,%2;" : "=l"(d) : "l"(a), "l"(b)); return d;
}
__device__ __forceinline__ ull mul2_(ull a, ull b) {
    ull d; asm("mul.rn.f32x2 %0,%1,%2;" : "=l"(d) : "l"(a), "l"(b)); return d;
}

__device__ __forceinline__ float tanh_a(float x) {   // HW MUFU tanh
    float y; asm("tanh.approx.f32 %0, %1;" : "=f"(y) : "f"(x)); return y;
}

__device__ __forceinline__ float wsum(float v) {
    v += __shfl_xor_sync(FULLMASK, v, 16);
    v += __shfl_xor_sync(FULLMASK, v, 8);
    v += __shfl_xor_sync(FULLMASK, v, 4);
    v += __shfl_xor_sync(FULLMASK, v, 2);
    v += __shfl_xor_sync(FULLMASK, v, 1);
    return v;
}
__device__ __forceinline__ ull wsum2(ull v) {
    v = add2_(v, __shfl_xor_sync(FULLMASK, v, 16));
    v = add2_(v, __shfl_xor_sync(FULLMASK, v, 8));
    v = add2_(v, __shfl_xor_sync(FULLMASK, v, 4));
    v = add2_(v, __shfl_xor_sync(FULLMASK, v, 2));
    v = add2_(v, __shfl_xor_sync(FULLMASK, v, 1));
    return v;
}

__device__ __forceinline__ float artanh_c(float z) {
    z = fminf(z, 1.0f - 1e-7f);
    return 0.5f * __logf(__fdividef(1.0f + z, 1.0f - z));
}
__device__ __forceinline__ float rnorm_c(float s2) {
    return rsqrtf(fmaxf(s2, 1e-30f));
}

// ------- T8 matvec (smem weights, smem xbuf stride XS) -------
template<int K, int SW, int R>
__device__ __forceinline__ void mvv(const float* __restrict__ Wc,
                                    const ull* __restrict__ xb,
                                    ull (&acc)[R][4]) {
    const int lane = threadIdx.x & 31;
#pragma unroll
    for (int r = 0; r < R; r++)
#pragma unroll
        for (int p = 0; p < 4; p++) acc[r][p] = 0ull;
    const float* wp = Wc + lane * SW;
#pragma unroll 4
    for (int k0 = 0; k0 < K; k0 += 4) {
        float4 wv[R];
#pragma unroll
        for (int r = 0; r < R; r++)
            wv[r] = *(const float4*)(wp + r * 32 * SW + k0);
#pragma unroll
        for (int kk = 0; kk < 4; kk++) {
            const ull* xr = xb + (k0 + kk) * XS;
            ulonglong2 xa = *(const ulonglong2*)(xr);
            ulonglong2 xc = *(const ulonglong2*)(xr + 2);
#pragma unroll
            for (int r = 0; r < R; r++) {
                float w = (kk == 0) ? wv[r].x : (kk == 1) ? wv[r].y
                        : (kk == 2) ? wv[r].z : wv[r].w;
                ull wd = pkd(w);
                acc[r][0] = fma2_(wd, xa.x, acc[r][0]);
                acc[r][1] = fma2_(wd, xa.y, acc[r][1]);
                acc[r][2] = fma2_(wd, xc.x, acc[r][2]);
                acc[r][3] = fma2_(wd, xc.y, acc[r][3]);
            }
        }
    }
}

template<int R>
__device__ __forceinline__ void ssq2(const ull (&v)[R][4], float (&o)[8]) {
#pragma unroll
    for (int p = 0; p < 4; p++) {
        ull a = 0ull;
#pragma unroll
        for (int r = 0; r < R; r++) a = fma2_(v[r][p], v[r][p], a);
        a = wsum2(a);
        upk2(a, o[2 * p], o[2 * p + 1]);
    }
}

template<int R>
__device__ __forceinline__ void scale2(ull (&v)[R][4], const float (&s)[8]) {
    ull sp[4];
#pragma unroll
    for (int p = 0; p < 4; p++) sp[p] = pk2(s[2 * p], s[2 * p + 1]);
#pragma unroll
    for (int r = 0; r < R; r++)
#pragma unroll
        for (int p = 0; p < 4; p++) v[r][p] = mul2_(v[r][p], sp[p]);
}

template<int R>
__device__ __forceinline__ void put2m(ull* xb, const ull (&v)[R][4], int rows) {
    const int lane = threadIdx.x & 31;
#pragma unroll
    for (int r = 0; r < R; r++) {
        int row = lane + 32 * r;
        if (row < rows) {
            ull* d = xb + row * XS;
            ulonglong2 a; a.x = v[r][0]; a.y = v[r][1];
            ulonglong2 c; c.x = v[r][2]; c.y = v[r][3];
            *(ulonglong2*)(d) = a;
            *(ulonglong2*)(d + 2) = c;
        }
    }
}

// expmap0 on packed regs, with analytic out-norm^2 carried
template<int R>
__device__ __forceinline__ void expmap2(ull (&v)[R][4], float (&xn2)[8]) {
    float s2[8];
    ssq2<R>(v, s2);
    float f[8];
#pragma unroll
    for (int t = 0; t < 8; t++) {
        float rn = rnorm_c(s2[t]);
        float n = fmaxf(s2[t], 1e-30f) * rn;
        float tt = tanh_a(kSQC() * n);
        float e = tt * rn * kISQC();
        float ny = tt * kISQC();
        float pg = (ny > kMaxN()) ? __fdividef(kMaxN(), ny) : 1.f;
        f[t] = e * pg;
        ny = fminf(ny, kMaxN());
        xn2[t] = ny * ny;
    }
    scale2<R>(v, f);
}

// p_linear tail: ONE reduction pass (||mv||², <mv,eb>), analytic mobius-add
template<int R>
__device__ __forceinline__ void hyplin_post(const float* __restrict__ eb, float ebn2,
                                            const float (&xn2)[8],
                                            ull (&out)[R][4], float (&on2raw)[8]) {
    const int lane = threadIdx.x & 31;
    float mn2[8], sme[8];
    {
        ull dm[4] = {0ull, 0ull, 0ull, 0ull};
        ull de[4] = {0ull, 0ull, 0ull, 0ull};
#pragma unroll
        for (int r = 0; r < R; r++) {
            ull ed = pkd(eb[lane + 32 * r]);
#pragma unroll
            for (int p = 0; p < 4; p++) {
                dm[p] = fma2_(out[r][p], out[r][p], dm[p]);
                de[p] = fma2_(out[r][p], ed, de[p]);
            }
        }
#pragma unroll
        for (int p = 0; p < 4; p++) {
            ull a = wsum2(dm[p]);
            upk2(a, mn2[2 * p], mn2[2 * p + 1]);
            ull c = wsum2(de[p]);
            upk2(c, sme[2 * p], sme[2 * p + 1]);
        }
    }
    ull A[4], B[4];
#pragma unroll
    for (int p = 0; p < 4; p++) {
        float a0[2], b0[2];
#pragma unroll
        for (int h = 0; h < 2; h++) {
            int t = 2 * p + h;
            float rxn = rnorm_c(xn2[t]);
            float xn = fmaxf(xn2[t], 1e-30f) * rxn;
            float rmn = rnorm_c(mn2[t]);
            float mn = fmaxf(mn2[t], 1e-30f) * rmn;
            float ar = artanh_c(kSQC() * xn);
            float tt = tanh_a(mn * rxn * ar);
            float sc = (mn2[t] == 0.f) ? 0.f : tt * rmn * kISQC();
            float nr = (mn2[t] == 0.f) ? 0.f : tt * kISQC();
            float g = (nr > kMaxN()) ? __fdividef(kMaxN(), nr) : 1.f;
            float tot = sc * g;
            nr = fminf(nr, kMaxN());
            float x2 = nr * nr;
            float xy = tot * sme[t];
            float ca = 1.f + 2.f * K_C * xy + K_C * ebn2;
            float cb = 1.f - K_C * x2;
            float dn = 1.f + 2.f * K_C * xy + K_C * K_C * x2 * ebn2;
            float iv = __fdividef(1.f, fmaxf(dn, K_MIN));
            on2raw[t] = iv * iv * (ca * ca * x2 + 2.f * ca * cb * xy + cb * cb * ebn2);
            a0[h] = ca * tot * iv;
            b0[h] = cb * iv;
        }
        A[p] = pk2(a0[0], a0[1]);
        B[p] = pk2(b0[0], b0[1]);
    }
#pragma unroll
    for (int r = 0; r < R; r++) {
        ull ed = pkd(eb[lane + 32 * r]);
#pragma unroll
        for (int p = 0; p < 4; p++)
            out[r][p] = fma2_(A[p], out[r][p], mul2_(B[p], ed));
    }
}

// Mob_Act(relu)
template<int R>
__device__ __forceinline__ void mobrelu2(ull (&v)[R][4], const float (&on2raw)[8],
                                         float (&xn2n)[8]) {
    float f[8];
#pragma unroll
    for (int t = 0; t < 8; t++) {
        float rn = rnorm_c(on2raw[t]);
        float n = fmaxf(on2raw[t], 1e-30f) * rn;
        float pf, nc, rnc;
        if (n > kMaxN()) { pf = __fdividef(kMaxN(), n); nc = kMaxN(); rnc = kIMaxN(); }
        else             { pf = 1.f; nc = n; rnc = rn; }
        float ls = artanh_c(kSQC() * nc) * rnc * kISQC();
        f[t] = pf * ls;
    }
    ull sp[4] = {0ull, 0ull, 0ull, 0ull};
#pragma unroll
    for (int p = 0; p < 4; p++) {
        ull fp = pk2(f[2 * p], f[2 * p + 1]);
#pragma unroll
        for (int r = 0; r < R; r++) {
            ull w = mul2_(v[r][p], fp);
            float a, b;
            upk2(w, a, b);
            a = fmaxf(a, 0.f);
            b = fmaxf(b, 0.f);
            w = pk2(a, b);
            v[r][p] = w;
            sp[p] = fma2_(w, w, sp[p]);
        }
    }
    float s2[8];
#pragma unroll
    for (int p = 0; p < 4; p++) {
        ull a = wsum2(sp[p]);
        upk2(a, s2[2 * p], s2[2 * p + 1]);
    }
#pragma unroll
    for (int t = 0; t < 8; t++) {
        float rn = rnorm_c(s2[t]);
        float n = fmaxf(s2[t], 1e-30f) * rn;
        float tt = tanh_a(kSQC() * n);
        float e = tt * rn * kISQC();
        float ny = tt * kISQC();
        float pg = (ny > kMaxN()) ? __fdividef(kMaxN(), ny) : 1.f;
        f[t] = e * pg;
        ny = fminf(ny, kMaxN());
        xn2n[t] = ny * ny;
    }
    scale2<R>(v, f);
}

// ---- cooperative smem loaders ----
__device__ __forceinline__ void loadWtCol(float* dst, const float* __restrict__ W,
                                          int J, int K, int Jrows, int SW) {
    int n = Jrows * SW;
    for (int i = threadIdx.x; i < n; i += blockDim.x) {
        int j = i / SW;
        int k = i - j * SW;
        dst[i] = (j < J && k < K) ? W[j * K + k] : 0.f;
    }
}
__device__ __forceinline__ void loadVec(float* dst, const float* __restrict__ v, int J, int Jpad) {
    for (int i = threadIdx.x; i < Jpad; i += blockDim.x) dst[i] = (i < J) ? v[i] : 0.f;
}

template<int R>
__device__ __forceinline__ void expmap_smem(float* v, float* n2out) {
    const int lane = threadIdx.x & 31;
    float a[R];
    float p = 0.f;
#pragma unroll
    for (int r = 0; r < R; r++) {
        a[r] = v[lane + 32 * r];
        p = fmaf(a[r], a[r], p);
    }
    p = wsum(p);
    float n = fmaxf(sqrtf(p), K_MIN);
    float tt = tanhf(fminf(kSQC() * n, 15.f));
    float scv = tt / (kSQC() * n);
#pragma unroll
    for (int r = 0; r < R; r++) a[r] *= scv;
    float q = 0.f;
#pragma unroll
    for (int r = 0; r < R; r++) q = fmaf(a[r], a[r], q);
    q = wsum(q);
    float nn = fmaxf(sqrtf(q), K_MIN);
    if (nn > kMaxN()) {
        float fsc = kMaxN() / nn;
#pragma unroll
        for (int r = 0; r < R; r++) a[r] *= fsc;
    }
    float y2 = 0.f;
#pragma unroll
    for (int r = 0; r < R; r++) y2 = fmaf(a[r], a[r], y2);
    y2 = wsum(y2);
#pragma unroll
    for (int r = 0; r < R; r++) v[lane + 32 * r] = a[r];
    if (lane == 0) *n2out = y2;
}

extern __shared__ float sm[];

// ============== Prologue: precompute attention algebra (parallel) ==============
__global__ void kPre_kernel(const float* __restrict__ Wae, const float* __restrict__ bae,
                            const float* __restrict__ bah,
                            const float* __restrict__ Wte, const float* __restrict__ Wth) {
    __shared__ float sb[128];
    __shared__ float n2s;
    const int tid = threadIdx.x;
    const int warp = tid >> 5, lane = tid & 31;
    if (tid < 128) sb[tid] = bah[tid];
    __syncthreads();
    if (warp == 0) expmap_smem<4>(sb, &n2s);
    __syncthreads();
    if (tid < 128) g_eb[tid] = sb[tid];
#pragma unroll
    for (int q = 0; q < 8; q++) {
        int t = warp * 8 + q;
        float p1 = 0.f, p2 = 0.f;
#pragma unroll
        for (int jj = 0; jj < 4; jj++) {
            int j = lane + 32 * jj;
            float w = Wae[j * 128 + t];
            p1 = fmaf(w, Wte[j], p1);
            p2 = fmaf(w, Wth[j], p2);
        }
        p1 = wsum(p1);
        p2 = wsum(p2);
        if (lane == 0) { g_u1[t] = p1; g_u2[t] = p2; }
    }
    if (warp == 0) {
        float a = 0.f, b = 0.f, c = 0.f, d = 0.f;
#pragma unroll
        for (int jj = 0; jj < 4; jj++) {
            int j = lane + 32 * jj;
            a = fmaf(Wte[j], bae[j], a);
            b = fmaf(Wth[j], bae[j], b);
            c = fmaf(Wte[j], sb[j], c);
            d = fmaf(Wth[j], sb[j], d);
        }
        a = wsum(a); b = wsum(b); c = wsum(c); d = wsum(d);
        if (lane == 0) {
            g_pre[0] = n2s;
            g_pre[1] = a; g_pre[2] = b; g_pre[3] = c; g_pre[4] = d;
        }
    }
}

// ===== Fused kernel EH: even blocks = Euclid path, odd blocks = hyperbolic ====
#define EH_B1 13824
#define EH_B2 13920
#define EH_B3 14048
#define EH_N2 14176
#define EH_U1 14180
#define EH_U2 14308
#define EH_XOFF 14436
__global__ void __launch_bounds__(512, 2) kEH_kernel(
    const float* __restrict__ x,
    const float* __restrict__ We1, const float* __restrict__ be1,
    const float* __restrict__ We2, const float* __restrict__ be2,
    const float* __restrict__ We3, const float* __restrict__ be3,
    const float* __restrict__ Wh1, const float* __restrict__ bh1,
    const float* __restrict__ Wh2, const float* __restrict__ bh2,
    const float* __restrict__ Wh3, const float* __restrict__ bh3) {
    const int lane = threadIdx.x & 31;
    const int warp = threadIdx.x >> 5;
    const int isH = blockIdx.x & 1;
    const int b = blockIdx.x >> 1;
    const int t0 = b * 128 + warp * 8;
    const int grp = t0 >> 3;
    ull* xb = (ull*)(sm + EH_XOFF) + warp * XBW_EH;

    if (!isH) {
        loadVec(sm + EH_B1, be1, 80, 96);
        loadVec(sm + EH_B2, be2, 104, 128);
        loadVec(sm + EH_B3, be3, 128, 128);
        loadVec(sm + EH_U1, g_u1, 128, 128);
        loadVec(sm + EH_U2, g_u2, 128, 128);
        loadWtCol(sm, We1, 80, 32, 96, 36);
        __syncthreads();

        {
            const int bb = t0 >> 7, s0 = t0 & 127;
            const float* xsrc = x + bb * (32 * 128) + lane * 128 + s0;
            float4 a0 = *(const float4*)(xsrc);
            float4 a1 = *(const float4*)(xsrc + 4);
            ull* d = xb + lane * XS;
            ulonglong2 u0; u0.x = pk2(a0.x, a0.y); u0.y = pk2(a0.z, a0.w);
            ulonglong2 u1; u1.x = pk2(a1.x, a1.y); u1.y = pk2(a1.z, a1.w);
            *(ulonglong2*)(d) = u0;
            *(ulonglong2*)(d + 2) = u1;
        }
        __syncwarp();

        ull h1[3][4];
        mvv<32, 36, 3>(sm, xb, h1);
#pragma unroll
        for (int r = 0; r < 3; r++) {
            float bv = sm[EH_B1 + lane + 32 * r];
#pragma unroll
            for (int p = 0; p < 4; p++) {
                float a, c;
                upk2(h1[r][p], a, c);
                h1[r][p] = pk2(fmaxf(a + bv, 0.f), fmaxf(c + bv, 0.f));
            }
        }
        put2m<3>(xb, h1, 104);
        __syncthreads();
        loadWtCol(sm, We2, 104, 80, 128, 84);
        __syncthreads();

        ull h2[4][4];
        mvv<80, 84, 4>(sm, xb, h2);
#pragma unroll
        for (int r = 0; r < 4; r++) {
            float bv = sm[EH_B2 + lane + 32 * r];
#pragma unroll
            for (int p = 0; p < 4; p++) {
                float a, c;
                upk2(h2[r][p], a, c);
                h2[r][p] = pk2(fmaxf(a + bv, 0.f), fmaxf(c + bv, 0.f));
            }
        }
        put2m<4>(xb, h2, 104);
        __syncthreads();
        loadWtCol(sm, We3, 128, 104, 128, 108);
        __syncthreads();

        ull h3[4][4];
        mvv<104, 108, 4>(sm, xb, h3);
        ull d1[4] = {0ull, 0ull, 0ull, 0ull};
        ull d2[4] = {0ull, 0ull, 0ull, 0ull};
        ull* dst = g_oe2 + (size_t)grp * 512;
#pragma unroll
        for (int r = 0; r < 4; r++) {
            int k = lane + 32 * r;
            float bv = sm[EH_B3 + k];
            ull w1d = pkd(sm[EH_U1 + k]);
            ull w2d = pkd(sm[EH_U2 + k]);
            ull vP[4];
#pragma unroll
            for (int p = 0; p < 4; p++) {
                float a, c;
                upk2(h3[r][p], a, c);
                ull v = pk2(fmaxf(a + bv, 0.f), fmaxf(c + bv, 0.f));
                vP[p] = v;
                d1[p] = fma2_(w1d, v, d1[p]);
                d2[p] = fma2_(w2d, v, d2[p]);
            }
            ull* dr = dst + k * 4;
            ulonglong2 u;
            u.x = vP[0]; u.y = vP[1];
            *(ulonglong2*)(dr) = u;
            u.x = vP[2]; u.y = vP[3];
            *(ulonglong2*)(dr + 2) = u;
        }
        const float c1 = g_pre[1], c2 = g_pre[2];
        float s1v[8], s2v[8];
#pragma unroll
        for (int p = 0; p < 4; p++) {
            ull a = wsum2(d1[p]);
            upk2(a, s1v[2 * p], s1v[2 * p + 1]);
            ull c = wsum2(d2[p]);
            upk2(c, s2v[2 * p], s2v[2 * p + 1]);
        }
#pragma unroll
        for (int t = 0; t < 8; t++)
            if (lane == t) {
                g_s1[t0 + t] = s1v[t] + c1;
                g_s2[t0 + t] = s2v[t] + c2;
            }
    } else {
        loadVec(sm + EH_B1, bh1, 80, 96);
        loadVec(sm + EH_B2, bh2, 104, 128);
        loadVec(sm + EH_B3, bh3, 128, 128);
        loadWtCol(sm, Wh1, 80, 32, 96, 36);
        __syncthreads();
        if (warp == 0) expmap_smem<3>(sm + EH_B1, sm + EH_N2 + 0);
        else if (warp == 1) expmap_smem<4>(sm + EH_B2, sm + EH_N2 + 1);
        else if (warp == 2) expmap_smem<4>(sm + EH_B3, sm + EH_N2 + 2);
        __syncthreads();
        const float e1n2 = sm[EH_N2 + 0], e2n2 = sm[EH_N2 + 1], e3n2 = sm[EH_N2 + 2];

        ull xh[1][4];
        {
            const int bb = t0 >> 7, s0 = t0 & 127;
            const float* xsrc = x + bb * (32 * 128) + lane * 128 + s0;
            float4 a0 = *(const float4*)(xsrc);
            float4 a1 = *(const float4*)(xsrc + 4);
            xh[0][0] = pk2(a0.x, a0.y);
            xh[0][1] = pk2(a0.z, a0.w);
            xh[0][2] = pk2(a1.x, a1.y);
            xh[0][3] = pk2(a1.z, a1.w);
        }
        float xn2[8];
        expmap2<1>(xh, xn2);
        __syncwarp();
        put2m<1>(xb, xh, 104);
        __syncwarp();

        ull y1[3][4];
        float on2[8];
        mvv<32, 36, 3>(sm, xb, y1);
        hyplin_post<3>(sm + EH_B1, e1n2, xn2, y1, on2);
        mobrelu2<3>(y1, on2, xn2);
        put2m<3>(xb, y1, 104);
        __syncthreads();
        loadWtCol(sm, Wh2, 104, 80, 128, 84);
        __syncthreads();

        ull y2[4][4];
        mvv<80, 84, 4>(sm, xb, y2);
        hyplin_post<4>(sm + EH_B2, e2n2, xn2, y2, on2);
        mobrelu2<4>(y2, on2, xn2);
        put2m<4>(xb, y2, 104);
        __syncthreads();
        loadWtCol(sm, Wh3, 128, 104, 128, 108);
        __syncthreads();

        ull y3[4][4];
        mvv<104, 108, 4>(sm, xb, y3);
        hyplin_post<4>(sm + EH_B3, e3n2, xn2, y3, on2);
        float pf[8], nn[8];
#pragma unroll
        for (int t = 0; t < 8; t++) {
            float rn = rnorm_c(on2[t]);
            float n = fmaxf(on2[t], 1e-30f) * rn;
            pf[t] = (n > kMaxN()) ? __fdividef(kMaxN(), n) : 1.f;
            float nc = fminf(n, kMaxN());
            nn[t] = nc * nc;
        }
        ull pf2[4];
#pragma unroll
        for (int p = 0; p < 4; p++) pf2[p] = pk2(pf[2 * p], pf[2 * p + 1]);
        ull* dst = g_oh2 + (size_t)grp * 512;
#pragma unroll
        for (int r = 0; r < 4; r++) {
            ull* dr = dst + (lane + 32 * r) * 4;
            ulonglong2 u;
            u.x = mul2_(y3[r][0], pf2[0]);
            u.y = mul2_(y3[r][1], pf2[1]);
            *(ulonglong2*)(dr) = u;
            u.x = mul2_(y3[r][2], pf2[2]);
            u.y = mul2_(y3[r][3], pf2[3]);
            *(ulonglong2*)(dr + 2) = u;
        }
#pragma unroll
        for (int t = 0; t < 8; t++)
            if (lane == t) g_ohn2[t0 + t] = nn[t];
    }
}

// ==== Kernel 2: Wah matvec + quad reduction + scalars + pooling + classifier ==
#define K2_W   0
#define K2_EB  16896
#define K2_WTE 17024
#define K2_WTH 17152
#define K2_OS  17280
#define K2_HS  17536
#define K2_XOFF 17552
__global__ void __launch_bounds__(512) k2_kernel(
    const float* __restrict__ Wah,
    const float* __restrict__ Wte, const float* __restrict__ bte,
    const float* __restrict__ Wth, const float* __restrict__ bth,
    const float* __restrict__ Wf1, const float* __restrict__ bf1,
    const float* __restrict__ Wf2, const float* __restrict__ bf2,
    float* __restrict__ out) {
    loadWtCol(sm + K2_W, Wah, 128, 128, 128, 132);
    loadVec(sm + K2_EB, g_eb, 128, 128);
    loadVec(sm + K2_WTE, Wte, 128, 128);
    loadVec(sm + K2_WTH, Wth, 128, 128);
    __syncthreads();
    const int warp = threadIdx.x >> 5;
    const int lane = threadIdx.x & 31;
    const float ebn2 = g_pre[0];
    const float wteeb = g_pre[3], wtheb = g_pre[4];
    const float bte0 = bte[0], bth0 = bth[0];
    const int t0 = blockIdx.x * 128 + warp * 8;
    const int grp = t0 >> 3;
    ull* xb = (ull*)(sm + K2_XOFF) + warp * XBW_K2;

    // ---- stage oh to xbuf; mv = Wah . oh ----
    {
        const ull* src = g_oh2 + (size_t)grp * 512;
#pragma unroll
        for (int r = 0; r < 4; r++) {
            int k = lane + 32 * r;
            ulonglong2 u0 = *(const ulonglong2*)(src + k * 4);
            ulonglong2 u1v = *(const ulonglong2*)(src + k * 4 + 2);
            ull* d = xb + k * XS;
            *(ulonglong2*)(d) = u0;
            *(ulonglong2*)(d + 2) = u1v;
        }
    }
    float xn2[8];
#pragma unroll
    for (int t = 0; t < 8; t++) xn2[t] = g_ohn2[t0 + t];
    __syncwarp();

    ull m[4][4];
    mvv<128, 132, 4>(sm + K2_W, xb, m);

    // ---- quad reduction on raw mv ----
    float mn2[8], sme[8], smt[8], smh[8];
    {
        ull dm[4] = {0ull, 0ull, 0ull, 0ull};
        ull de[4] = {0ull, 0ull, 0ull, 0ull};
        ull dt[4] = {0ull, 0ull, 0ull, 0ull};
        ull dh[4] = {0ull, 0ull, 0ull, 0ull};
#pragma unroll
        for (int r = 0; r < 4; r++) {
            int k = lane + 32 * r;
            ull ed = pkd(sm[K2_EB + k]);
            ull td = pkd(sm[K2_WTE + k]);
            ull hd = pkd(sm[K2_WTH + k]);
#pragma unroll
            for (int p = 0; p < 4; p++) {
                dm[p] = fma2_(m[r][p], m[r][p], dm[p]);
                de[p] = fma2_(m[r][p], ed, de[p]);
                dt[p] = fma2_(m[r][p], td, dt[p]);
                dh[p] = fma2_(m[r][p], hd, dh[p]);
            }
        }
#pragma unroll
        for (int p = 0; p < 4; p++) {
            ull a = wsum2(dm[p]); upk2(a, mn2[2 * p], mn2[2 * p + 1]);
            ull c = wsum2(de[p]); upk2(c, sme[2 * p], sme[2 * p + 1]);
            ull e = wsum2(dt[p]); upk2(e, smt[2 * p], smt[2 * p + 1]);
            ull g = wsum2(dh[p]); upk2(g, smh[2 * p], smh[2 * p + 1]);
        }
    }

    // ---- per-token scalars ----
    float w0[8], w1[8];
#pragma unroll
    for (int t = 0; t < 8; t++) {
        float rxn = rnorm_c(xn2[t]);
        float xn = fmaxf(xn2[t], 1e-30f) * rxn;
        float rmn = rnorm_c(mn2[t]);
        float mn = fmaxf(mn2[t], 1e-30f) * rmn;
        float ar = artanh_c(kSQC() * xn);
        float tth = tanh_a(mn * rxn * ar);
        float scv = (mn2[t] == 0.f) ? 0.f : tth * rmn * kISQC();
        float nr = (mn2[t] == 0.f) ? 0.f : tth * kISQC();
        float g = (nr > kMaxN()) ? __fdividef(kMaxN(), nr) : 1.f;
        float tot = scv * g;
        nr = fminf(nr, kMaxN());
        float x2 = nr * nr;
        float xy = tot * sme[t];
        float ca = 1.f + 2.f * K_C * xy + K_C * ebn2;
        float cb = 1.f - K_C * x2;
        float dn = 1.f + 2.f * K_C * xy + K_C * K_C * x2 * ebn2;
        float iv = __fdividef(1.f, fmaxf(dn, K_MIN));
        float on2 = iv * iv * (ca * ca * x2 + 2.f * ca * cb * xy + cb * cb * ebn2);
        float Af = ca * tot * iv;
        float Bf = cb * iv;
        float rn = rnorm_c(on2);
        float n = fmaxf(on2, 1e-30f) * rn;
        float pf, nc, rnc;
        if (n > kMaxN()) { pf = __fdividef(kMaxN(), n); nc = kMaxN(); rnc = kIMaxN(); }
        else             { pf = 1.f; nc = n; rnc = rn; }
        float f = pf * (artanh_c(kSQC() * nc) * rnc * kISQC());
        float s3 = f * (Af * smt[t] + Bf * wteeb);   // Wte . th
        float s4 = f * (Af * smh[t] + Bf * wtheb);   // Wth . th
        float aet = 0.5f * (g_s1[t0 + t] - s3) + bte0;
        float aht = 0.5f * (s4 - g_s2[t0 + t]) + bth0;
        float mx = fmaxf(aet, aht);
        float e0 = __expf(aet - mx), e1 = __expf(aht - mx);
        float inv = __fdividef(1.f, e0 + e1);
        w0[t] = e0 * inv;
        w1[t] = e1 * inv;
    }

    // ---- proc_e = w0 * out_e (stream from g_oe2), pool ----
    float acce[4];
    {
        const ull* pe = g_oe2 + (size_t)grp * 512;
        ull w0p[4];
#pragma unroll
        for (int p = 0; p < 4; p++) w0p[p] = pk2(w0[2 * p], w0[2 * p + 1]);
#pragma unroll
        for (int r = 0; r < 4; r++) {
            int k = lane + 32 * r;
            ulonglong2 u0 = *(const ulonglong2*)(pe + k * 4);
            ulonglong2 u1v = *(const ulonglong2*)(pe + k * 4 + 2);
            ull a = mul2_(w0p[0], u0.x);
            a = fma2_(w0p[1], u0.y, a);
            a = fma2_(w0p[2], u1v.x, a);
            a = fma2_(w0p[3], u1v.y, a);
            float x0, x1;
            upk2(a, x0, x1);
            acce[r] = x0 + x1;
        }
    }

    // ---- proc_h = logmap0(projx(mobius_scalar_mul(w1, out_h))), pool ----
    float acch[4];
    {
        float tt[8];
#pragma unroll
        for (int t = 0; t < 8; t++) {
            float rn = rnorm_c(xn2[t]);
            float n = fmaxf(xn2[t], 1e-30f) * rn;
            float ar = artanh_c(kSQC() * n);
            float q = tanh_a(w1[t] * ar);
            float scv = q * rn * kISQC();
            float qn = q * kISQC();
            float pg = (qn > kMaxN()) ? __fdividef(kMaxN(), qn) : 1.f;
            float qc = fmaxf(fminf(qn, kMaxN()), K_MIN);
            float ls = artanh_c(kSQC() * qc) * __fdividef(1.f, kSQC() * qc);
            tt[t] = scv * pg * ls;
        }
        ull tp[4];
#pragma unroll
        for (int p = 0; p < 4; p++) tp[p] = pk2(tt[2 * p], tt[2 * p + 1]);
#pragma unroll
        for (int r = 0; r < 4; r++) {
            const ull* d = xb + (lane + 32 * r) * XS;
            ulonglong2 u0 = *(const ulonglong2*)(d);
            ulonglong2 u1v = *(const ulonglong2*)(d + 2);
            ull a = mul2_(tp[0], u0.x);
            a = fma2_(tp[1], u0.y, a);
            a = fma2_(tp[2], u1v.x, a);
            a = fma2_(tp[3], u1v.y, a);
            float x0, x1;
            upk2(a, x0, x1);
            acch[r] = x0 + x1;
        }
    }

    float* pes = sm + K2_XOFF;          // dead xbuf reuse
    float* phs = pes + 2048;
    __syncthreads();
#pragma unroll
    for (int r = 0; r < 4; r++) {
        pes[warp * 128 + lane + 32 * r] = acce[r];
        phs[warp * 128 + lane + 32 * r] = acch[r];
    }
    __syncthreads();

    float* os = sm + K2_OS;
    float* hs = sm + K2_HS;
    for (int j = threadIdx.x; j < 256; j += 512) {
        const float* src = (j < 128) ? (pes + j) : (phs + (j - 128));
        float s = 0.f;
#pragma unroll
        for (int i = 0; i < 16; i++) s += src[i * 128];
        os[j] = s * (1.0f / 128.0f);
    }
    __syncthreads();

    if (threadIdx.x < 32) {
        if (lane < 10) {
            float h = bf1[lane];
            for (int i = 0; i < 256; i++) h = fmaf(Wf1[lane * 256 + i], os[i], h);
            hs[lane] = fmaxf(h, 0.f);
        }
        __syncwarp();
        if (lane < 10) {
            float o2 = bf2[lane];
#pragma unroll
            for (int i = 0; i < 10; i++) o2 = fmaf(Wf2[lane * 10 + i], hs[i], o2);
            out[blockIdx.x * 10 + lane] = o2;
        }
    }
}

extern "C" void kernel_launch(void* const* d_in, const int* in_sizes, int n_in,
                              void* d_out, int out_size) {
    (void)in_sizes; (void)n_in; (void)out_size;
    const float* x   = (const float*)d_in[0];
    const float* We1 = (const float*)d_in[1];  const float* be1 = (const float*)d_in[2];
    const float* We2 = (const float*)d_in[3];  const float* be2 = (const float*)d_in[4];
    const float* We3 = (const float*)d_in[5];  const float* be3 = (const float*)d_in[6];
    const float* Wh1 = (const float*)d_in[7];  const float* bh1 = (const float*)d_in[8];
    const float* Wh2 = (const float*)d_in[9];  const float* bh2 = (const float*)d_in[10];
    const float* Wh3 = (const float*)d_in[11]; const float* bh3 = (const float*)d_in[12];
    const float* Wae = (const float*)d_in[13]; const float* bae = (const float*)d_in[14];
    const float* Wah = (const float*)d_in[15]; const float* bah = (const float*)d_in[16];
    const float* Wte = (const float*)d_in[17]; const float* bte = (const float*)d_in[18];
    const float* Wth = (const float*)d_in[19]; const float* bth = (const float*)d_in[20];
    const float* Wf1 = (const float*)d_in[21]; const float* bf1 = (const float*)d_in[22];
    const float* Wf2 = (const float*)d_in[23]; const float* bf2 = (const float*)d_in[24];
    float* out = (float*)d_out;

    size_t smEH = (size_t)(EH_XOFF + 16 * XBW_EH * 2) * sizeof(float);  // ~111 KB
    size_t sm2  = (size_t)(K2_XOFF + 16 * XBW_K2 * 2) * sizeof(float);  // ~136 KB

    cudaFuncSetAttribute(kEH_kernel, cudaFuncAttributeMaxDynamicSharedMemorySize, (int)smEH);
    cudaFuncSetAttribute(k2_kernel, cudaFuncAttributeMaxDynamicSharedMemorySize, (int)sm2);

    kPre_kernel<<<1, 512>>>(Wae, bae, bah, Wte, Wth);
    kEH_kernel<<<2 * NB, 512, smEH>>>(x, We1, be1, We2, be2, We3, be3,
                                      Wh1, bh1, Wh2, bh2, Wh3, bh3);
    k2_kernel<<<NB, 512, sm2>>>(Wah, Wte, bte, Wth, bth,
                                Wf1, bf1, Wf2, bf2, out);
}

// round 15
// speedup vs baseline: 1.0830x; 1.0108x over previous
#include <cuda_runtime.h>

typedef unsigned long long ull;

#define FULLMASK 0xffffffffu
#define NB 1024
#define SQ 128
#define K_C   1.2f
#define K_MIN 1e-15f
#define XS 4        // ull stride per k-row (32B)
#define XBW_EH 416  // kEH: 104 rows * XS per warp
#define XBW_K2 512  // k2: 128 rows * XS per warp

__device__ __forceinline__ float kSQC()   { return 1.0954451150103321f; }
__device__ __forceinline__ float kISQC()  { return 0.9128709291752769f; }
__device__ __forceinline__ float kMaxN()  { return 0.90921944545857576f; }
__device__ __forceinline__ float kIMaxN() { return 1.0998446018140677f; }

// packed inter-kernel scratch: token-group g = t0/8; index g*512 + k*4 + p
__device__ ull g_oe2[(NB * SQ / 8) * 512];
__device__ ull g_oh2[(NB * SQ / 8) * 512];
__device__ float g_ohn2[NB * SQ];
__device__ float g_s1[NB * SQ];   // u1.oe + Wte.bae  (per token)
__device__ float g_s2[NB * SQ];   // u2.oe + Wth.bae
// prologue-precomputed attention algebra
__device__ float g_u1[128];   // Wae^T * Wte
__device__ float g_u2[128];   // Wae^T * Wth
__device__ float g_eb[128];   // expmap0(bah)
__device__ float g_pre[8];    // [0]=ebn2 [1]=Wte.bae [2]=Wth.bae [3]=Wte.eb [4]=Wth.eb

// ---------------- packed f32x2 helpers ----------------
__device__ __forceinline__ ull pk2(float a, float b) {
    ull r; asm("mov.b64 %0,{%1,%2};" : "=l"(r) : "f"(a), "f"(b)); return r;
}
__device__ __forceinline__ ull pkd(float a) { return pk2(a, a); }
__device__ __forceinline__ void upk2(ull v, float& a, float& b) {
    asm("mov.b64 {%0,%1},%2;" : "=f"(a), "=f"(b) : "l"(v));
}
__device__ __forceinline__ ull fma2_(ull a, ull b, ull c) {
    ull d; asm("fma.rn.f32x2 %0,%1,%2,%3;" : "=l"(d) : "l"(a), "l"(b), "l"(c)); return d;
}
__device__ __forceinline__ ull add2_(ull a, ull b) {
    ull d; asm("add.rn.f32x2 %0,%1,%2;" : "=l"(d) : "l"(a), "l"(b)); return d;
}
__device__ __forceinline__ ull mul2_(ull a, ull b) {
    ull d; asm("mul.rn.f32x2 %0,%1,%2;" : "=l"(d) : "l"(a), "l"(b)); return d;
}

__device__ __forceinline__ float tanh_a(float x) {   // HW MUFU tanh
    float y; asm("tanh.approx.f32 %0, %1;" : "=f"(y) : "f"(x)); return y;
}

__device__ __forceinline__ float wsum(float v) {
    v += __shfl_xor_sync(FULLMASK, v, 16);
    v += __shfl_xor_sync(FULLMASK, v, 8);
    v += __shfl_xor_sync(FULLMASK, v, 4);
    v += __shfl_xor_sync(FULLMASK, v, 2);
    v += __shfl_xor_sync(FULLMASK, v, 1);
    return v;
}
__device__ __forceinline__ ull wsum2(ull v) {
    v = add2_(v, __shfl_xor_sync(FULLMASK, v, 16));
    v = add2_(v, __shfl_xor_sync(FULLMASK, v, 8));
    v = add2_(v, __shfl_xor_sync(FULLMASK, v, 4));
    v = add2_(v, __shfl_xor_sync(FULLMASK, v, 2));
    v = add2_(v, __shfl_xor_sync(FULLMASK, v, 1));
    return v;
}

__device__ __forceinline__ float artanh_c(float z) {
    z = fminf(z, 1.0f - 1e-7f);
    return 0.5f * __logf(__fdividef(1.0f + z, 1.0f - z));
}
__device__ __forceinline__ float rnorm_c(float s2) {
    return rsqrtf(fmaxf(s2, 1e-30f));
}

// ------- T8 matvec (smem weights, smem xbuf stride XS) -------
template<int K, int SW, int R>
__device__ __forceinline__ void mvv(const float* __restrict__ Wc,
                                    const ull* __restrict__ xb,
                                    ull (&acc)[R][4]) {
    const int lane = threadIdx.x & 31;
#pragma unroll
    for (int r = 0; r < R; r++)
#pragma unroll
        for (int p = 0; p < 4; p++) acc[r][p] = 0ull;
    const float* wp = Wc + lane * SW;
#pragma unroll 4
    for (int k0 = 0; k0 < K; k0 += 4) {
        float4 wv[R];
#pragma unroll
        for (int r = 0; r < R; r++)
            wv[r] = *(const float4*)(wp + r * 32 * SW + k0);
#pragma unroll
        for (int kk = 0; kk < 4; kk++) {
            const ull* xr = xb + (k0 + kk) * XS;
            ulonglong2 xa = *(const ulonglong2*)(xr);
            ulonglong2 xc = *(const ulonglong2*)(xr + 2);
#pragma unroll
            for (int r = 0; r < R; r++) {
                float w = (kk == 0) ? wv[r].x : (kk == 1) ? wv[r].y
                        : (kk == 2) ? wv[r].z : wv[r].w;
                ull wd = pkd(w);
                acc[r][0] = fma2_(wd, xa.x, acc[r][0]);
                acc[r][1] = fma2_(wd, xa.y, acc[r][1]);
                acc[r][2] = fma2_(wd, xc.x, acc[r][2]);
                acc[r][3] = fma2_(wd, xc.y, acc[r][3]);
            }
        }
    }
}

template<int R>
__device__ __forceinline__ void ssq2(const ull (&v)[R][4], float (&o)[8]) {
#pragma unroll
    for (int p = 0; p < 4; p++) {
        ull a = 0ull;
#pragma unroll
        for (int r = 0; r < R; r++) a = fma2_(v[r][p], v[r][p], a);
        a = wsum2(a);
        upk2(a, o[2 * p], o[2 * p + 1]);
    }
}

template<int R>
__device__ __forceinline__ void scale2(ull (&v)[R][4], const float (&s)[8]) {
    ull sp[4];
#pragma unroll
    for (int p = 0; p < 4; p++) sp[p] = pk2(s[2 * p], s[2 * p + 1]);
#pragma unroll
    for (int r = 0; r < R; r++)
#pragma unroll
        for (int p = 0; p < 4; p++) v[r][p] = mul2_(v[r][p], sp[p]);
}

template<int R>
__device__ __forceinline__ void put2m(ull* xb, const ull (&v)[R][4], int rows) {
    const int lane = threadIdx.x & 31;
#pragma unroll
    for (int r = 0; r < R; r++) {
        int row = lane + 32 * r;
        if (row < rows) {
            ull* d = xb + row * XS;
            ulonglong2 a; a.x = v[r][0]; a.y = v[r][1];
            ulonglong2 c; c.x = v[r][2]; c.y = v[r][3];
            *(ulonglong2*)(d) = a;
            *(ulonglong2*)(d + 2) = c;
        }
    }
}

// expmap0 on packed regs, with analytic out-norm^2 carried
template<int R>
__device__ __forceinline__ void expmap2(ull (&v)[R][4], float (&xn2)[8]) {
    float s2[8];
    ssq2<R>(v, s2);
    float f[8];
#pragma unroll
    for (int t = 0; t < 8; t++) {
        float rn = rnorm_c(s2[t]);
        float n = fmaxf(s2[t], 1e-30f) * rn;
        float tt = tanh_a(kSQC() * n);
        float e = tt * rn * kISQC();
        float ny = tt * kISQC();
        float pg = (ny > kMaxN()) ? __fdividef(kMaxN(), ny) : 1.f;
        f[t] = e * pg;
        ny = fminf(ny, kMaxN());
        xn2[t] = ny * ny;
    }
    scale2<R>(v, f);
}

// p_linear tail: ONE reduction pass (||mv||², <mv,eb>), analytic mobius-add
template<int R>
__device__ __forceinline__ void hyplin_post(const float* __restrict__ eb, float ebn2,
                                            const float (&xn2)[8],
                                            ull (&out)[R][4], float (&on2raw)[8]) {
    const int lane = threadIdx.x & 31;
    float mn2[8], sme[8];
    {
        ull dm[4] = {0ull, 0ull, 0ull, 0ull};
        ull de[4] = {0ull, 0ull, 0ull, 0ull};
#pragma unroll
        for (int r = 0; r < R; r++) {
            ull ed = pkd(eb[lane + 32 * r]);
#pragma unroll
            for (int p = 0; p < 4; p++) {
                dm[p] = fma2_(out[r][p], out[r][p], dm[p]);
                de[p] = fma2_(out[r][p], ed, de[p]);
            }
        }
#pragma unroll
        for (int p = 0; p < 4; p++) {
            ull a = wsum2(dm[p]);
            upk2(a, mn2[2 * p], mn2[2 * p + 1]);
            ull c = wsum2(de[p]);
            upk2(c, sme[2 * p], sme[2 * p + 1]);
        }
    }
    ull A[4], B[4];
#pragma unroll
    for (int p = 0; p < 4; p++) {
        float a0[2], b0[2];
#pragma unroll
        for (int h = 0; h < 2; h++) {
            int t = 2 * p + h;
            float rxn = rnorm_c(xn2[t]);
            float xn = fmaxf(xn2[t], 1e-30f) * rxn;
            float rmn = rnorm_c(mn2[t]);
            float mn = fmaxf(mn2[t], 1e-30f) * rmn;
            float ar = artanh_c(kSQC() * xn);
            float tt = tanh_a(mn * rxn * ar);
            float sc = (mn2[t] == 0.f) ? 0.f : tt * rmn * kISQC();
            float nr = (mn2[t] == 0.f) ? 0.f : tt * kISQC();
            float g = (nr > kMaxN()) ? __fdividef(kMaxN(), nr) : 1.f;
            float tot = sc * g;
            nr = fminf(nr, kMaxN());
            float x2 = nr * nr;
            float xy = tot * sme[t];
            float ca = 1.f + 2.f * K_C * xy + K_C * ebn2;
            float cb = 1.f - K_C * x2;
            float dn = 1.f + 2.f * K_C * xy + K_C * K_C * x2 * ebn2;
            float iv = __fdividef(1.f, fmaxf(dn, K_MIN));
            on2raw[t] = iv * iv * (ca * ca * x2 + 2.f * ca * cb * xy + cb * cb * ebn2);
            a0[h] = ca * tot * iv;
            b0[h] = cb * iv;
        }
        A[p] = pk2(a0[0], a0[1]);
        B[p] = pk2(b0[0], b0[1]);
    }
#pragma unroll
    for (int r = 0; r < R; r++) {
        ull ed = pkd(eb[lane + 32 * r]);
#pragma unroll
        for (int p = 0; p < 4; p++)
            out[r][p] = fma2_(A[p], out[r][p], mul2_(B[p], ed));
    }
}

// Mob_Act(relu)
template<int R>
__device__ __forceinline__ void mobrelu2(ull (&v)[R][4], const float (&on2raw)[8],
                                         float (&xn2n)[8]) {
    float f[8];
#pragma unroll
    for (int t = 0; t < 8; t++) {
        float rn = rnorm_c(on2raw[t]);
        float n = fmaxf(on2raw[t], 1e-30f) * rn;
        float pf, nc, rnc;
        if (n > kMaxN()) { pf = __fdividef(kMaxN(), n); nc = kMaxN(); rnc = kIMaxN(); }
        else             { pf = 1.f; nc = n; rnc = rn; }
        float ls = artanh_c(kSQC() * nc) * rnc * kISQC();
        f[t] = pf * ls;
    }
    ull sp[4] = {0ull, 0ull, 0ull, 0ull};
#pragma unroll
    for (int p = 0; p < 4; p++) {
        ull fp = pk2(f[2 * p], f[2 * p + 1]);
#pragma unroll
        for (int r = 0; r < R; r++) {
            ull w = mul2_(v[r][p], fp);
            float a, b;
            upk2(w, a, b);
            a = fmaxf(a, 0.f);
            b = fmaxf(b, 0.f);
            w = pk2(a, b);
            v[r][p] = w;
            sp[p] = fma2_(w, w, sp[p]);
        }
    }
    float s2[8];
#pragma unroll
    for (int p = 0; p < 4; p++) {
        ull a = wsum2(sp[p]);
        upk2(a, s2[2 * p], s2[2 * p + 1]);
    }
#pragma unroll
    for (int t = 0; t < 8; t++) {
        float rn = rnorm_c(s2[t]);
        float n = fmaxf(s2[t], 1e-30f) * rn;
        float tt = tanh_a(kSQC() * n);
        float e = tt * rn * kISQC();
        float ny = tt * kISQC();
        float pg = (ny > kMaxN()) ? __fdividef(kMaxN(), ny) : 1.f;
        f[t] = e * pg;
        ny = fminf(ny, kMaxN());
        xn2n[t] = ny * ny;
    }
    scale2<R>(v, f);
}

// ---- cooperative smem loaders ----
__device__ __forceinline__ void loadWtCol(float* dst, const float* __restrict__ W,
                                          int J, int K, int Jrows, int SW) {
    int n = Jrows * SW;
    for (int i = threadIdx.x; i < n; i += blockDim.x) {
        int j = i / SW;
        int k = i - j * SW;
        dst[i] = (j < J && k < K) ? W[j * K + k] : 0.f;
    }
}
__device__ __forceinline__ void loadVec(float* dst, const float* __restrict__ v, int J, int Jpad) {
    for (int i = threadIdx.x; i < Jpad; i += blockDim.x) dst[i] = (i < J) ? v[i] : 0.f;
}

template<int R>
__device__ __forceinline__ void expmap_smem(float* v, float* n2out) {
    const int lane = threadIdx.x & 31;
    float a[R];
    float p = 0.f;
#pragma unroll
    for (int r = 0; r < R; r++) {
        a[r] = v[lane + 32 * r];
        p = fmaf(a[r], a[r], p);
    }
    p = wsum(p);
    float n = fmaxf(sqrtf(p), K_MIN);
    float tt = tanhf(fminf(kSQC() * n, 15.f));
    float scv = tt / (kSQC() * n);
#pragma unroll
    for (int r = 0; r < R; r++) a[r] *= scv;
    float q = 0.f;
#pragma unroll
    for (int r = 0; r < R; r++) q = fmaf(a[r], a[r], q);
    q = wsum(q);
    float nn = fmaxf(sqrtf(q), K_MIN);
    if (nn > kMaxN()) {
        float fsc = kMaxN() / nn;
#pragma unroll
        for (int r = 0; r < R; r++) a[r] *= fsc;
    }
    float y2 = 0.f;
#pragma unroll
    for (int r = 0; r < R; r++) y2 = fmaf(a[r], a[r], y2);
    y2 = wsum(y2);
#pragma unroll
    for (int r = 0; r < R; r++) v[lane + 32 * r] = a[r];
    if (lane == 0) *n2out = y2;
}

extern __shared__ float sm[];

// ====== Prologue: precompute attention algebra (coalesced Wae streaming) ======
__global__ void kPre_kernel(const float* __restrict__ Wae, const float* __restrict__ bae,
                            const float* __restrict__ bah,
                            const float* __restrict__ Wte, const float* __restrict__ Wth) {
    __shared__ float sb[128];
    __shared__ float part1[512];
    __shared__ float part2[512];
    __shared__ float n2s;
    const int tid = threadIdx.x;
    const int warp = tid >> 5, lane = tid & 31;
    if (tid < 128) sb[tid] = bah[tid];
    __syncthreads();
    if (warp == 0) expmap_smem<4>(sb, &n2s);
    __syncthreads();
    if (tid < 128) g_eb[tid] = sb[tid];
    // u1/u2: thread owns column t = tid&127, j-chunk tid>>7; coalesced Wae reads
    {
        const int t = tid & 127, ch = tid >> 7;
        float p1 = 0.f, p2 = 0.f;
#pragma unroll 8
        for (int jj = 0; jj < 32; jj++) {
            int j = ch * 32 + jj;
            float w = Wae[j * 128 + t];
            p1 = fmaf(w, Wte[j], p1);
            p2 = fmaf(w, Wth[j], p2);
        }
        part1[tid] = p1;
        part2[tid] = p2;
    }
    __syncthreads();
    if (tid < 128) {
        g_u1[tid] = part1[tid] + part1[tid + 128] + part1[tid + 256] + part1[tid + 384];
        g_u2[tid] = part2[tid] + part2[tid + 128] + part2[tid + 256] + part2[tid + 384];
    }
    if (warp == 0) {
        float a = 0.f, b = 0.f, c = 0.f, d = 0.f;
#pragma unroll
        for (int jj = 0; jj < 4; jj++) {
            int j = lane + 32 * jj;
            a = fmaf(Wte[j], bae[j], a);
            b = fmaf(Wth[j], bae[j], b);
            c = fmaf(Wte[j], sb[j], c);
            d = fmaf(Wth[j], sb[j], d);
        }
        a = wsum(a); b = wsum(b); c = wsum(c); d = wsum(d);
        if (lane == 0) {
            g_pre[0] = n2s;
            g_pre[1] = a; g_pre[2] = b; g_pre[3] = c; g_pre[4] = d;
        }
    }
}

// ===== Fused kernel EH: even blocks = Euclid path, odd blocks = hyperbolic ====
#define EH_B1 13824
#define EH_B2 13920
#define EH_B3 14048
#define EH_N2 14176
#define EH_U1 14180
#define EH_U2 14308
#define EH_XOFF 14436
__global__ void __launch_bounds__(512, 2) kEH_kernel(
    const float* __restrict__ x,
    const float* __restrict__ We1, const float* __restrict__ be1,
    const float* __restrict__ We2, const float* __restrict__ be2,
    const float* __restrict__ We3, const float* __restrict__ be3,
    const float* __restrict__ Wh1, const float* __restrict__ bh1,
    const float* __restrict__ Wh2, const float* __restrict__ bh2,
    const float* __restrict__ Wh3, const float* __restrict__ bh3) {
    const int lane = threadIdx.x & 31;
    const int warp = threadIdx.x >> 5;
    const int isH = blockIdx.x & 1;
    const int b = blockIdx.x >> 1;
    const int t0 = b * 128 + warp * 8;
    const int grp = t0 >> 3;
    ull* xb = (ull*)(sm + EH_XOFF) + warp * XBW_EH;

    if (!isH) {
        loadVec(sm + EH_B1, be1, 80, 96);
        loadVec(sm + EH_B2, be2, 104, 128);
        loadVec(sm + EH_B3, be3, 128, 128);
        loadVec(sm + EH_U1, g_u1, 128, 128);
        loadVec(sm + EH_U2, g_u2, 128, 128);
        loadWtCol(sm, We1, 80, 32, 96, 36);
        __syncthreads();

        {
            const int bb = t0 >> 7, s0 = t0 & 127;
            const float* xsrc = x + bb * (32 * 128) + lane * 128 + s0;
            float4 a0 = *(const float4*)(xsrc);
            float4 a1 = *(const float4*)(xsrc + 4);
            ull* d = xb + lane * XS;
            ulonglong2 u0; u0.x = pk2(a0.x, a0.y); u0.y = pk2(a0.z, a0.w);
            ulonglong2 u1; u1.x = pk2(a1.x, a1.y); u1.y = pk2(a1.z, a1.w);
            *(ulonglong2*)(d) = u0;
            *(ulonglong2*)(d + 2) = u1;
        }
        __syncwarp();

        ull h1[3][4];
        mvv<32, 36, 3>(sm, xb, h1);
#pragma unroll
        for (int r = 0; r < 3; r++) {
            float bv = sm[EH_B1 + lane + 32 * r];
#pragma unroll
            for (int p = 0; p < 4; p++) {
                float a, c;
                upk2(h1[r][p], a, c);
                h1[r][p] = pk2(fmaxf(a + bv, 0.f), fmaxf(c + bv, 0.f));
            }
        }
        put2m<3>(xb, h1, 104);
        __syncthreads();
        loadWtCol(sm, We2, 104, 80, 128, 84);
        __syncthreads();

        ull h2[4][4];
        mvv<80, 84, 4>(sm, xb, h2);
#pragma unroll
        for (int r = 0; r < 4; r++) {
            float bv = sm[EH_B2 + lane + 32 * r];
#pragma unroll
            for (int p = 0; p < 4; p++) {
                float a, c;
                upk2(h2[r][p], a, c);
                h2[r][p] = pk2(fmaxf(a + bv, 0.f), fmaxf(c + bv, 0.f));
            }
        }
        put2m<4>(xb, h2, 104);
        __syncthreads();
        loadWtCol(sm, We3, 128, 104, 128, 108);
        __syncthreads();

        ull h3[4][4];
        mvv<104, 108, 4>(sm, xb, h3);
        ull d1[4] = {0ull, 0ull, 0ull, 0ull};
        ull d2[4] = {0ull, 0ull, 0ull, 0ull};
        ull* dst = g_oe2 + (size_t)grp * 512;
#pragma unroll
        for (int r = 0; r < 4; r++) {
            int k = lane + 32 * r;
            float bv = sm[EH_B3 + k];
            ull w1d = pkd(sm[EH_U1 + k]);
            ull w2d = pkd(sm[EH_U2 + k]);
            ull vP[4];
#pragma unroll
            for (int p = 0; p < 4; p++) {
                float a, c;
                upk2(h3[r][p], a, c);
                ull v = pk2(fmaxf(a + bv, 0.f), fmaxf(c + bv, 0.f));
                vP[p] = v;
                d1[p] = fma2_(w1d, v, d1[p]);
                d2[p] = fma2_(w2d, v, d2[p]);
            }
            ull* dr = dst + k * 4;
            ulonglong2 u;
            u.x = vP[0]; u.y = vP[1];
            *(ulonglong2*)(dr) = u;
            u.x = vP[2]; u.y = vP[3];
            *(ulonglong2*)(dr + 2) = u;
        }
        const float c1 = g_pre[1], c2 = g_pre[2];
        float s1v[8], s2v[8];
#pragma unroll
        for (int p = 0; p < 4; p++) {
            ull a = wsum2(d1[p]);
            upk2(a, s1v[2 * p], s1v[2 * p + 1]);
            ull c = wsum2(d2[p]);
            upk2(c, s2v[2 * p], s2v[2 * p + 1]);
        }
#pragma unroll
        for (int t = 0; t < 8; t++)
            if (lane == t) {
                g_s1[t0 + t] = s1v[t] + c1;
                g_s2[t0 + t] = s2v[t] + c2;
            }
    } else {
        loadVec(sm + EH_B1, bh1, 80, 96);
        loadVec(sm + EH_B2, bh2, 104, 128);
        loadVec(sm + EH_B3, bh3, 128, 128);
        loadWtCol(sm, Wh1, 80, 32, 96, 36);
        __syncthreads();
        if (warp == 0) expmap_smem<3>(sm + EH_B1, sm + EH_N2 + 0);
        else if (warp == 1) expmap_smem<4>(sm + EH_B2, sm + EH_N2 + 1);
        else if (warp == 2) expmap_smem<4>(sm + EH_B3, sm + EH_N2 + 2);
        __syncthreads();
        const float e1n2 = sm[EH_N2 + 0], e2n2 = sm[EH_N2 + 1], e3n2 = sm[EH_N2 + 2];

        ull xh[1][4];
        {
            const int bb = t0 >> 7, s0 = t0 & 127;
            const float* xsrc = x + bb * (32 * 128) + lane * 128 + s0;
            float4 a0 = *(const float4*)(xsrc);
            float4 a1 = *(const float4*)(xsrc + 4);
            xh[0][0] = pk2(a0.x, a0.y);
            xh[0][1] = pk2(a0.z, a0.w);
            xh[0][2] = pk2(a1.x, a1.y);
            xh[0][3] = pk2(a1.z, a1.w);
        }
        float xn2[8];
        expmap2<1>(xh, xn2);
        __syncwarp();
        put2m<1>(xb, xh, 104);
        __syncwarp();

        ull y1[3][4];
        float on2[8];
        mvv<32, 36, 3>(sm, xb, y1);
        hyplin_post<3>(sm + EH_B1, e1n2, xn2, y1, on2);
        mobrelu2<3>(y1, on2, xn2);
        put2m<3>(xb, y1, 104);
        __syncthreads();
        loadWtCol(sm, Wh2, 104, 80, 128, 84);
        __syncthreads();

        ull y2[4][4];
        mvv<80, 84, 4>(sm, xb, y2);
        hyplin_post<4>(sm + EH_B2, e2n2, xn2, y2, on2);
        mobrelu2<4>(y2, on2, xn2);
        put2m<4>(xb, y2, 104);
        __syncthreads();
        loadWtCol(sm, Wh3, 128, 104, 128, 108);
        __syncthreads();

        ull y3[4][4];
        mvv<104, 108, 4>(sm, xb, y3);
        hyplin_post<4>(sm + EH_B3, e3n2, xn2, y3, on2);
        float pf[8], nn[8];
#pragma unroll
        for (int t = 0; t < 8; t++) {
            float rn = rnorm_c(on2[t]);
            float n = fmaxf(on2[t], 1e-30f) * rn;
            pf[t] = (n > kMaxN()) ? __fdividef(kMaxN(), n) : 1.f;
            float nc = fminf(n, kMaxN());
            nn[t] = nc * nc;
        }
        ull pf2[4];
#pragma unroll
        for (int p = 0; p < 4; p++) pf2[p] = pk2(pf[2 * p], pf[2 * p + 1]);
        ull* dst = g_oh2 + (size_t)grp * 512;
#pragma unroll
        for (int r = 0; r < 4; r++) {
            ull* dr = dst + (lane + 32 * r) * 4;
            ulonglong2 u;
            u.x = mul2_(y3[r][0], pf2[0]);
            u.y = mul2_(y3[r][1], pf2[1]);
            *(ulonglong2*)(dr) = u;
            u.x = mul2_(y3[r][2], pf2[2]);
            u.y = mul2_(y3[r][3], pf2[3]);
            *(ulonglong2*)(dr + 2) = u;
        }
#pragma unroll
        for (int t = 0; t < 8; t++)
            if (lane == t) g_ohn2[t0 + t] = nn[t];
    }
}

// ==== Kernel 2: Wah matvec + quad reduction + scalars + pooling + classifier ==
#define K2_W   0
#define K2_EB  16896
#define K2_WTE 17024
#define K2_WTH 17152
#define K2_OS  17280
#define K2_HS  17536
#define K2_XOFF 17552
__global__ void __launch_bounds__(512) k2_kernel(
    const float* __restrict__ Wah,
    const float* __restrict__ Wte, const float* __restrict__ bte,
    const float* __restrict__ Wth, const float* __restrict__ bth,
    const float* __restrict__ Wf1, const float* __restrict__ bf1,
    const float* __restrict__ Wf2, const float* __restrict__ bf2,
    float* __restrict__ out) {
    loadWtCol(sm + K2_W, Wah, 128, 128, 128, 132);
    loadVec(sm + K2_EB, g_eb, 128, 128);
    loadVec(sm + K2_WTE, Wte, 128, 128);
    loadVec(sm + K2_WTH, Wth, 128, 128);
    __syncthreads();
    const int warp = threadIdx.x >> 5;
    const int lane = threadIdx.x & 31;
    const float ebn2 = g_pre[0];
    const float wteeb = g_pre[3], wtheb = g_pre[4];
    const float bte0 = bte[0], bth0 = bth[0];
    const int t0 = blockIdx.x * 128 + warp * 8;
    const int grp = t0 >> 3;
    ull* xb = (ull*)(sm + K2_XOFF) + warp * XBW_K2;

    // ---- stage oh to xbuf; mv = Wah . oh ----
    {
        const ull* src = g_oh2 + (size_t)grp * 512;
#pragma unroll
        for (int r = 0; r < 4; r++) {
            int k = lane + 32 * r;
            ulonglong2 u0 = *(const ulonglong2*)(src + k * 4);
            ulonglong2 u1v = *(const ulonglong2*)(src + k * 4 + 2);
            ull* d = xb + k * XS;
            *(ulonglong2*)(d) = u0;
            *(ulonglong2*)(d + 2) = u1v;
        }
    }
    float xn2[8];
#pragma unroll
    for (int t = 0; t < 8; t++) xn2[t] = g_ohn2[t0 + t];
    __syncwarp();

    ull m[4][4];
    mvv<128, 132, 4>(sm + K2_W, xb, m);

    // ---- quad reduction on raw mv ----
    float mn2[8], sme[8], smt[8], smh[8];
    {
        ull dm[4] = {0ull, 0ull, 0ull, 0ull};
        ull de[4] = {0ull, 0ull, 0ull, 0ull};
        ull dt[4] = {0ull, 0ull, 0ull, 0ull};
        ull dh[4] = {0ull, 0ull, 0ull, 0ull};
#pragma unroll
        for (int r = 0; r < 4; r++) {
            int k = lane + 32 * r;
            ull ed = pkd(sm[K2_EB + k]);
            ull td = pkd(sm[K2_WTE + k]);
            ull hd = pkd(sm[K2_WTH + k]);
#pragma unroll
            for (int p = 0; p < 4; p++) {
                dm[p] = fma2_(m[r][p], m[r][p], dm[p]);
                de[p] = fma2_(m[r][p], ed, de[p]);
                dt[p] = fma2_(m[r][p], td, dt[p]);
                dh[p] = fma2_(m[r][p], hd, dh[p]);
            }
        }
#pragma unroll
        for (int p = 0; p < 4; p++) {
            ull a = wsum2(dm[p]); upk2(a, mn2[2 * p], mn2[2 * p + 1]);
            ull c = wsum2(de[p]); upk2(c, sme[2 * p], sme[2 * p + 1]);
            ull e = wsum2(dt[p]); upk2(e, smt[2 * p], smt[2 * p + 1]);
            ull g = wsum2(dh[p]); upk2(g, smh[2 * p], smh[2 * p + 1]);
        }
    }

    // ---- per-token scalars ----
    float w0[8], w1[8];
#pragma unroll
    for (int t = 0; t < 8; t++) {
        float rxn = rnorm_c(xn2[t]);
        float xn = fmaxf(xn2[t], 1e-30f) * rxn;
        float rmn = rnorm_c(mn2[t]);
        float mn = fmaxf(mn2[t], 1e-30f) * rmn;
        float ar = artanh_c(kSQC() * xn);
        float tth = tanh_a(mn * rxn * ar);
        float scv = (mn2[t] == 0.f) ? 0.f : tth * rmn * kISQC();
        float nr = (mn2[t] == 0.f) ? 0.f : tth * kISQC();
        float g = (nr > kMaxN()) ? __fdividef(kMaxN(), nr) : 1.f;
        float tot = scv * g;
        nr = fminf(nr, kMaxN());
        float x2 = nr * nr;
        float xy = tot * sme[t];
        float ca = 1.f + 2.f * K_C * xy + K_C * ebn2;
        float cb = 1.f - K_C * x2;
        float dn = 1.f + 2.f * K_C * xy + K_C * K_C * x2 * ebn2;
        float iv = __fdividef(1.f, fmaxf(dn, K_MIN));
        float on2 = iv * iv * (ca * ca * x2 + 2.f * ca * cb * xy + cb * cb * ebn2);
        float Af = ca * tot * iv;
        float Bf = cb * iv;
        float rn = rnorm_c(on2);
        float n = fmaxf(on2, 1e-30f) * rn;
        float pf, nc, rnc;
        if (n > kMaxN()) { pf = __fdividef(kMaxN(), n); nc = kMaxN(); rnc = kIMaxN(); }
        else             { pf = 1.f; nc = n; rnc = rn; }
        float f = pf * (artanh_c(kSQC() * nc) * rnc * kISQC());
        float s3 = f * (Af * smt[t] + Bf * wteeb);   // Wte . th
        float s4 = f * (Af * smh[t] + Bf * wtheb);   // Wth . th
        float aet = 0.5f * (g_s1[t0 + t] - s3) + bte0;
        float aht = 0.5f * (s4 - g_s2[t0 + t]) + bth0;
        float mx = fmaxf(aet, aht);
        float e0 = __expf(aet - mx), e1 = __expf(aht - mx);
        float inv = __fdividef(1.f, e0 + e1);
        w0[t] = e0 * inv;
        w1[t] = e1 * inv;
    }

    // ---- proc_e = w0 * out_e (stream from g_oe2), pool ----
    float acce[4];
    {
        const ull* pe = g_oe2 + (size_t)grp * 512;
        ull w0p[4];
#pragma unroll
        for (int p = 0; p < 4; p++) w0p[p] = pk2(w0[2 * p], w0[2 * p + 1]);
#pragma unroll
        for (int r = 0; r < 4; r++) {
            int k = lane + 32 * r;
            ulonglong2 u0 = *(const ulonglong2*)(pe + k * 4);
            ulonglong2 u1v = *(const ulonglong2*)(pe + k * 4 + 2);
            ull a = mul2_(w0p[0], u0.x);
            a = fma2_(w0p[1], u0.y, a);
            a = fma2_(w0p[2], u1v.x, a);
            a = fma2_(w0p[3], u1v.y, a);
            float x0, x1;
            upk2(a, x0, x1);
            acce[r] = x0 + x1;
        }
    }

    // ---- proc_h = logmap0(projx(mobius_scalar_mul(w1, out_h))), pool ----
    float acch[4];
    {
        float tt[8];
#pragma unroll
        for (int t = 0; t < 8; t++) {
            float rn = rnorm_c(xn2[t]);
            float n = fmaxf(xn2[t], 1e-30f) * rn;
            float ar = artanh_c(kSQC() * n);
            float q = tanh_a(w1[t] * ar);
            float scv = q * rn * kISQC();
            float qn = q * kISQC();
            float pg = (qn > kMaxN()) ? __fdividef(kMaxN(), qn) : 1.f;
            float qc = fmaxf(fminf(qn, kMaxN()), K_MIN);
            float ls = artanh_c(kSQC() * qc) * __fdividef(1.f, kSQC() * qc);
            tt[t] = scv * pg * ls;
        }
        ull tp[4];
#pragma unroll
        for (int p = 0; p < 4; p++) tp[p] = pk2(tt[2 * p], tt[2 * p + 1]);
#pragma unroll
        for (int r = 0; r < 4; r++) {
            const ull* d = xb + (lane + 32 * r) * XS;
            ulonglong2 u0 = *(const ulonglong2*)(d);
            ulonglong2 u1v = *(const ulonglong2*)(d + 2);
            ull a = mul2_(tp[0], u0.x);
            a = fma2_(tp[1], u0.y, a);
            a = fma2_(tp[2], u1v.x, a);
            a = fma2_(tp[3], u1v.y, a);
            float x0, x1;
            upk2(a, x0, x1);
            acch[r] = x0 + x1;
        }
    }

    float* pes = sm + K2_XOFF;          // dead xbuf reuse
    float* phs = pes + 2048;
    __syncthreads();
#pragma unroll
    for (int r = 0; r < 4; r++) {
        pes[warp * 128 + lane + 32 * r] = acce[r];
        phs[warp * 128 + lane + 32 * r] = acch[r];
    }
    __syncthreads();

    float* os = sm + K2_OS;
    float* hs = sm + K2_HS;
    for (int j = threadIdx.x; j < 256; j += 512) {
        const float* src = (j < 128) ? (pes + j) : (phs + (j - 128));
        float s = 0.f;
#pragma unroll
        for (int i = 0; i < 16; i++) s += src[i * 128];
        os[j] = s * (1.0f / 128.0f);
    }
    __syncthreads();

    if (threadIdx.x < 32) {
        if (lane < 10) {
            float h = bf1[lane];
            for (int i = 0; i < 256; i++) h = fmaf(Wf1[lane * 256 + i], os[i], h);
            hs[lane] = fmaxf(h, 0.f);
        }
        __syncwarp();
        if (lane < 10) {
            float o2 = bf2[lane];
#pragma unroll
            for (int i = 0; i < 10; i++) o2 = fmaf(Wf2[lane * 10 + i], hs[i], o2);
            out[blockIdx.x * 10 + lane] = o2;
        }
    }
}

extern "C" void kernel_launch(void* const* d_in, const int* in_sizes, int n_in,
                              void* d_out, int out_size) {
    (void)in_sizes; (void)n_in; (void)out_size;
    const float* x   = (const float*)d_in[0];
    const float* We1 = (const float*)d_in[1];  const float* be1 = (const float*)d_in[2];
    const float* We2 = (const float*)d_in[3];  const float* be2 = (const float*)d_in[4];
    const float* We3 = (const float*)d_in[5];  const float* be3 = (const float*)d_in[6];
    const float* Wh1 = (const float*)d_in[7];  const float* bh1 = (const float*)d_in[8];
    const float* Wh2 = (const float*)d_in[9];  const float* bh2 = (const float*)d_in[10];
    const float* Wh3 = (const float*)d_in[11]; const float* bh3 = (const float*)d_in[12];
    const float* Wae = (const float*)d_in[13]; const float* bae = (const float*)d_in[14];
    const float* Wah = (const float*)d_in[15]; const float* bah = (const float*)d_in[16];
    const float* Wte = (const float*)d_in[17]; const float* bte = (const float*)d_in[18];
    const float* Wth = (const float*)d_in[19]; const float* bth = (const float*)d_in[20];
    const float* Wf1 = (const float*)d_in[21]; const float* bf1 = (const float*)d_in[22];
    const float* Wf2 = (const float*)d_in[23]; const float* bf2 = (const float*)d_in[24];
    float* out = (float*)d_out;

    size_t smEH = (size_t)(EH_XOFF + 16 * XBW_EH * 2) * sizeof(float);  // ~111 KB
    size_t sm2  = (size_t)(K2_XOFF + 16 * XBW_K2 * 2) * sizeof(float);  // ~136 KB

    cudaFuncSetAttribute(kEH_kernel, cudaFuncAttributeMaxDynamicSharedMemorySize, (int)smEH);
    cudaFuncSetAttribute(k2_kernel, cudaFuncAttributeMaxDynamicSharedMemorySize, (int)sm2);

    kPre_kernel<<<1, 512>>>(Wae, bae, bah, Wte, Wth);
    kEH_kernel<<<2 * NB, 512, smEH>>>(x, We1, be1, We2, be2, We3, be3,
                                      Wh1, bh1, Wh2, bh2, Wh3, bh3);
    k2_kernel<<<NB, 512, sm2>>>(Wah, Wte, bte, Wth, bth,
                                Wf1, bf1, Wf2, bf2, out);
}

// round 16
// speedup vs baseline: 1.1082x; 1.0233x over previous
#include <cuda_runtime.h>

typedef unsigned long long ull;

#define FULLMASK 0xffffffffu
#define NB 1024
#define SQ 128
#define K_C   1.2f
#define K_MIN 1e-15f
#define XS 4        // ull stride per k-row (32B)
#define XBW_EH 416  // kEH: 104 rows * XS per warp
#define XBW_K2 512  // k2: 128 rows * XS per warp

__device__ __forceinline__ float kSQC()    { return 1.0954451150103321f; }
__device__ __forceinline__ float kISQC()   { return 0.9128709291752769f; }
__device__ __forceinline__ float kMaxN()   { return 0.90921944545857576f; }
__device__ __forceinline__ float kClampT() { return 0.996f; }   // kMaxN*kSQC

// packed inter-kernel scratch: token-group g = t0/8; index g*512 + k*4 + p
__device__ ull g_oe2[(NB * SQ / 8) * 512];
__device__ ull g_oh2[(NB * SQ / 8) * 512];
__device__ float g_ohn2[NB * SQ];
__device__ float g_s1[NB * SQ];   // u1.oe + Wte.bae  (per token)
__device__ float g_s2[NB * SQ];   // u2.oe + Wth.bae
// prologue-precomputed attention algebra
__device__ float g_u1[128];   // Wae^T * Wte
__device__ float g_u2[128];   // Wae^T * Wth
__device__ float g_eb[128];   // expmap0(bah)
__device__ float g_pre[8];    // [0]=ebn2 [1]=Wte.bae [2]=Wth.bae [3]=Wte.eb [4]=Wth.eb

// ---------------- packed f32x2 helpers ----------------
__device__ __forceinline__ ull pk2(float a, float b) {
    ull r; asm("mov.b64 %0,{%1,%2};" : "=l"(r) : "f"(a), "f"(b)); return r;
}
__device__ __forceinline__ ull pkd(float a) { return pk2(a, a); }
__device__ __forceinline__ void upk2(ull v, float& a, float& b) {
    asm("mov.b64 {%0,%1},%2;" : "=f"(a), "=f"(b) : "l"(v));
}
__device__ __forceinline__ ull fma2_(ull a, ull b, ull c) {
    ull d; asm("fma.rn.f32x2 %0,%1,%2,%3;" : "=l"(d) : "l"(a), "l"(b), "l"(c)); return d;
}
__device__ __forceinline__ ull add2_(ull a, ull b) {
    ull d; asm("add.rn.f32x2 %0,%1,%2;" : "=l"(d) : "l"(a), "l"(b)); return d;
}
__device__ __forceinline__ ull mul2_(ull a, ull b) {
    ull d; asm("mul.rn.f32x2 %0,%1,%2;" : "=l"(d) : "l"(a), "l"(b)); return d;
}

__device__ __forceinline__ float tanh_a(float x) {   // HW MUFU tanh
    float y; asm("tanh.approx.f32 %0, %1;" : "=f"(y) : "f"(x)); return y;
}

__device__ __forceinline__ float wsum(float v) {
    v += __shfl_xor_sync(FULLMASK, v, 16);
    v += __shfl_xor_sync(FULLMASK, v, 8);
    v += __shfl_xor_sync(FULLMASK, v, 4);
    v += __shfl_xor_sync(FULLMASK, v, 2);
    v += __shfl_xor_sync(FULLMASK, v, 1);
    return v;
}
__device__ __forceinline__ ull wsum2(ull v) {
    v = add2_(v, __shfl_xor_sync(FULLMASK, v, 16));
    v = add2_(v, __shfl_xor_sync(FULLMASK, v, 8));
    v = add2_(v, __shfl_xor_sync(FULLMASK, v, 4));
    v = add2_(v, __shfl_xor_sync(FULLMASK, v, 2));
    v = add2_(v, __shfl_xor_sync(FULLMASK, v, 1));
    return v;
}

__device__ __forceinline__ float artanh_c(float z) {
    z = fminf(z, 1.0f - 1e-7f);
    return 0.5f * __logf(__fdividef(1.0f + z, 1.0f - z));
}
__device__ __forceinline__ float rnorm_c(float s2) {
    return rsqrtf(fmaxf(s2, 1e-30f));
}

// ------- T8 matvec (smem weights, smem xbuf stride XS) -------
template<int K, int SW, int R>
__device__ __forceinline__ void mvv(const float* __restrict__ Wc,
                                    const ull* __restrict__ xb,
                                    ull (&acc)[R][4]) {
    const int lane = threadIdx.x & 31;
#pragma unroll
    for (int r = 0; r < R; r++)
#pragma unroll
        for (int p = 0; p < 4; p++) acc[r][p] = 0ull;
    const float* wp = Wc + lane * SW;
#pragma unroll 4
    for (int k0 = 0; k0 < K; k0 += 4) {
        float4 wv[R];
#pragma unroll
        for (int r = 0; r < R; r++)
            wv[r] = *(const float4*)(wp + r * 32 * SW + k0);
#pragma unroll
        for (int kk = 0; kk < 4; kk++) {
            const ull* xr = xb + (k0 + kk) * XS;
            ulonglong2 xa = *(const ulonglong2*)(xr);
            ulonglong2 xc = *(const ulonglong2*)(xr + 2);
#pragma unroll
            for (int r = 0; r < R; r++) {
                float w = (kk == 0) ? wv[r].x : (kk == 1) ? wv[r].y
                        : (kk == 2) ? wv[r].z : wv[r].w;
                ull wd = pkd(w);
                acc[r][0] = fma2_(wd, xa.x, acc[r][0]);
                acc[r][1] = fma2_(wd, xa.y, acc[r][1]);
                acc[r][2] = fma2_(wd, xc.x, acc[r][2]);
                acc[r][3] = fma2_(wd, xc.y, acc[r][3]);
            }
        }
    }
}

template<int R>
__device__ __forceinline__ void ssq2(const ull (&v)[R][4], float (&o)[8]) {
#pragma unroll
    for (int p = 0; p < 4; p++) {
        ull a = 0ull;
#pragma unroll
        for (int r = 0; r < R; r++) a = fma2_(v[r][p], v[r][p], a);
        a = wsum2(a);
        upk2(a, o[2 * p], o[2 * p + 1]);
    }
}

template<int R>
__device__ __forceinline__ void scale2(ull (&v)[R][4], const float (&s)[8]) {
    ull sp[4];
#pragma unroll
    for (int p = 0; p < 4; p++) sp[p] = pk2(s[2 * p], s[2 * p + 1]);
#pragma unroll
    for (int r = 0; r < R; r++)
#pragma unroll
        for (int p = 0; p < 4; p++) v[r][p] = mul2_(v[r][p], sp[p]);
}

template<int R>
__device__ __forceinline__ void put2m(ull* xb, const ull (&v)[R][4], int rows) {
    const int lane = threadIdx.x & 31;
#pragma unroll
    for (int r = 0; r < R; r++) {
        int row = lane + 32 * r;
        if (row < rows) {
            ull* d = xb + row * XS;
            ulonglong2 a; a.x = v[r][0]; a.y = v[r][1];
            ulonglong2 c; c.x = v[r][2]; c.y = v[r][3];
            *(ulonglong2*)(d) = a;
            *(ulonglong2*)(d + 2) = c;
        }
    }
}

// expmap0 on packed regs; divide-free projx via min-clamp
template<int R>
__device__ __forceinline__ void expmap2(ull (&v)[R][4], float (&xn2)[8]) {
    float s2[8];
    ssq2<R>(v, s2);
    float f[8];
#pragma unroll
    for (int t = 0; t < 8; t++) {
        float rn = rnorm_c(s2[t]);
        float n = fmaxf(s2[t], 1e-30f) * rn;
        float tt = tanh_a(kSQC() * n);
        f[t] = rn * kISQC() * fminf(tt, kClampT());
        float ny = fminf(tt * kISQC(), kMaxN());
        xn2[t] = ny * ny;
    }
    scale2<R>(v, f);
}

// p_linear tail: ONE reduction pass; divide-free clamps
template<int R>
__device__ __forceinline__ void hyplin_post(const float* __restrict__ eb, float ebn2,
                                            const float (&xn2)[8],
                                            ull (&out)[R][4], float (&on2raw)[8]) {
    const int lane = threadIdx.x & 31;
    float mn2[8], sme[8];
    {
        ull dm[4] = {0ull, 0ull, 0ull, 0ull};
        ull de[4] = {0ull, 0ull, 0ull, 0ull};
#pragma unroll
        for (int r = 0; r < R; r++) {
            ull ed = pkd(eb[lane + 32 * r]);
#pragma unroll
            for (int p = 0; p < 4; p++) {
                dm[p] = fma2_(out[r][p], out[r][p], dm[p]);
                de[p] = fma2_(out[r][p], ed, de[p]);
            }
        }
#pragma unroll
        for (int p = 0; p < 4; p++) {
            ull a = wsum2(dm[p]);
            upk2(a, mn2[2 * p], mn2[2 * p + 1]);
            ull c = wsum2(de[p]);
            upk2(c, sme[2 * p], sme[2 * p + 1]);
        }
    }
    ull A[4], B[4];
#pragma unroll
    for (int p = 0; p < 4; p++) {
        float a0[2], b0[2];
#pragma unroll
        for (int h = 0; h < 2; h++) {
            int t = 2 * p + h;
            float rxn = rnorm_c(xn2[t]);
            float xn = fmaxf(xn2[t], 1e-30f) * rxn;
            float rmn = rnorm_c(mn2[t]);
            float mn = fmaxf(mn2[t], 1e-30f) * rmn;
            float ar = artanh_c(kSQC() * xn);
            float tt = tanh_a(mn * rxn * ar);
            float tot = rmn * kISQC() * fminf(tt, kClampT());
            float nr = fminf(tt * kISQC(), kMaxN());
            float x2 = nr * nr;
            float xy = tot * sme[t];
            float ca = 1.f + 2.f * K_C * xy + K_C * ebn2;
            float cb = 1.f - K_C * x2;
            float dn = 1.f + 2.f * K_C * xy + K_C * K_C * x2 * ebn2;
            float iv = __fdividef(1.f, fmaxf(dn, K_MIN));
            on2raw[t] = iv * iv * (ca * ca * x2 + 2.f * ca * cb * xy + cb * cb * ebn2);
            a0[h] = ca * tot * iv;
            b0[h] = cb * iv;
        }
        A[p] = pk2(a0[0], a0[1]);
        B[p] = pk2(b0[0], b0[1]);
    }
#pragma unroll
    for (int r = 0; r < R; r++) {
        ull ed = pkd(eb[lane + 32 * r]);
#pragma unroll
        for (int p = 0; p < 4; p++)
            out[r][p] = fma2_(A[p], out[r][p], mul2_(B[p], ed));
    }
}

// Mob_Act(relu): f-carry (relu commutes with positive scale), divide-free
template<int R>
__device__ __forceinline__ void mobrelu2(ull (&v)[R][4], const float (&on2raw)[8],
                                         float (&xn2n)[8]) {
    float f1[8];
#pragma unroll
    for (int t = 0; t < 8; t++) {
        float rn = rnorm_c(on2raw[t]);
        float n = fmaxf(on2raw[t], 1e-30f) * rn;
        float nc = fminf(n, kMaxN());
        f1[t] = artanh_c(kSQC() * nc) * rn * kISQC();   // pf*ls folded
    }
    // relu WITHOUT f1 (carried analytically), raw ssq
    ull sp[4] = {0ull, 0ull, 0ull, 0ull};
#pragma unroll
    for (int p = 0; p < 4; p++) {
#pragma unroll
        for (int r = 0; r < R; r++) {
            float a, b;
            upk2(v[r][p], a, b);
            a = fmaxf(a, 0.f);
            b = fmaxf(b, 0.f);
            ull w = pk2(a, b);
            v[r][p] = w;
            sp[p] = fma2_(w, w, sp[p]);
        }
    }
    float s2r[8];
#pragma unroll
    for (int p = 0; p < 4; p++) {
        ull a = wsum2(sp[p]);
        upk2(a, s2r[2 * p], s2r[2 * p + 1]);
    }
    float F[8];
#pragma unroll
    for (int t = 0; t < 8; t++) {
        float rnr = rnorm_c(s2r[t]);
        float n2 = f1[t] * (fmaxf(s2r[t], 1e-30f) * rnr);   // = f1 * ||relu||
        float tt = tanh_a(kSQC() * n2);
        F[t] = rnr * kISQC() * fminf(tt, kClampT());        // f1*f2 combined
        float ny = fminf(tt * kISQC(), kMaxN());
        xn2n[t] = ny * ny;
    }
    scale2<R>(v, F);
}

// ---- cooperative smem loaders ----
__device__ __forceinline__ void loadWtCol(float* dst, const float* __restrict__ W,
                                          int J, int K, int Jrows, int SW) {
    int n = Jrows * SW;
    for (int i = threadIdx.x; i < n; i += blockDim.x) {
        int j = i / SW;
        int k = i - j * SW;
        dst[i] = (j < J && k < K) ? W[j * K + k] : 0.f;
    }
}
__device__ __forceinline__ void loadVec(float* dst, const float* __restrict__ v, int J, int Jpad) {
    for (int i = threadIdx.x; i < Jpad; i += blockDim.x) dst[i] = (i < J) ? v[i] : 0.f;
}

template<int R>
__device__ __forceinline__ void expmap_smem(float* v, float* n2out) {
    const int lane = threadIdx.x & 31;
    float a[R];
    float p = 0.f;
#pragma unroll
    for (int r = 0; r < R; r++) {
        a[r] = v[lane + 32 * r];
        p = fmaf(a[r], a[r], p);
    }
    p = wsum(p);
    float n = fmaxf(sqrtf(p), K_MIN);
    float tt = tanhf(fminf(kSQC() * n, 15.f));
    float scv = tt / (kSQC() * n);
#pragma unroll
    for (int r = 0; r < R; r++) a[r] *= scv;
    float q = 0.f;
#pragma unroll
    for (int r = 0; r < R; r++) q = fmaf(a[r], a[r], q);
    q = wsum(q);
    float nn = fmaxf(sqrtf(q), K_MIN);
    if (nn > kMaxN()) {
        float fsc = kMaxN() / nn;
#pragma unroll
        for (int r = 0; r < R; r++) a[r] *= fsc;
    }
    float y2 = 0.f;
#pragma unroll
    for (int r = 0; r < R; r++) y2 = fmaf(a[r], a[r], y2);
    y2 = wsum(y2);
#pragma unroll
    for (int r = 0; r < R; r++) v[lane + 32 * r] = a[r];
    if (lane == 0) *n2out = y2;
}

extern __shared__ float sm[];

// ====== Prologue: precompute attention algebra (coalesced Wae streaming) ======
__global__ void kPre_kernel(const float* __restrict__ Wae, const float* __restrict__ bae,
                            const float* __restrict__ bah,
                            const float* __restrict__ Wte, const float* __restrict__ Wth) {
    __shared__ float sb[128];
    __shared__ float part1[512];
    __shared__ float part2[512];
    __shared__ float n2s;
    const int tid = threadIdx.x;
    const int warp = tid >> 5, lane = tid & 31;
    if (tid < 128) sb[tid] = bah[tid];
    __syncthreads();
    if (warp == 0) expmap_smem<4>(sb, &n2s);
    __syncthreads();
    if (tid < 128) g_eb[tid] = sb[tid];
    {
        const int t = tid & 127, ch = tid >> 7;
        float p1 = 0.f, p2 = 0.f;
#pragma unroll 8
        for (int jj = 0; jj < 32; jj++) {
            int j = ch * 32 + jj;
            float w = Wae[j * 128 + t];
            p1 = fmaf(w, Wte[j], p1);
            p2 = fmaf(w, Wth[j], p2);
        }
        part1[tid] = p1;
        part2[tid] = p2;
    }
    __syncthreads();
    if (tid < 128) {
        g_u1[tid] = part1[tid] + part1[tid + 128] + part1[tid + 256] + part1[tid + 384];
        g_u2[tid] = part2[tid] + part2[tid + 128] + part2[tid + 256] + part2[tid + 384];
    }
    if (warp == 0) {
        float a = 0.f, b = 0.f, c = 0.f, d = 0.f;
#pragma unroll
        for (int jj = 0; jj < 4; jj++) {
            int j = lane + 32 * jj;
            a = fmaf(Wte[j], bae[j], a);
            b = fmaf(Wth[j], bae[j], b);
            c = fmaf(Wte[j], sb[j], c);
            d = fmaf(Wth[j], sb[j], d);
        }
        a = wsum(a); b = wsum(b); c = wsum(c); d = wsum(d);
        if (lane == 0) {
            g_pre[0] = n2s;
            g_pre[1] = a; g_pre[2] = b; g_pre[3] = c; g_pre[4] = d;
        }
    }
}

// ===== Fused kernel EH: even blocks = Euclid path, odd blocks = hyperbolic ====
#define EH_B1 13824
#define EH_B2 13920
#define EH_B3 14048
#define EH_N2 14176
#define EH_U1 14180
#define EH_U2 14308
#define EH_XOFF 14436
__global__ void __launch_bounds__(512, 2) kEH_kernel(
    const float* __restrict__ x,
    const float* __restrict__ We1, const float* __restrict__ be1,
    const float* __restrict__ We2, const float* __restrict__ be2,
    const float* __restrict__ We3, const float* __restrict__ be3,
    const float* __restrict__ Wh1, const float* __restrict__ bh1,
    const float* __restrict__ Wh2, const float* __restrict__ bh2,
    const float* __restrict__ Wh3, const float* __restrict__ bh3) {
    const int lane = threadIdx.x & 31;
    const int warp = threadIdx.x >> 5;
    const int isH = blockIdx.x & 1;
    const int b = blockIdx.x >> 1;
    const int t0 = b * 128 + warp * 8;
    const int grp = t0 >> 3;
    ull* xb = (ull*)(sm + EH_XOFF) + warp * XBW_EH;

    if (!isH) {
        loadVec(sm + EH_B1, be1, 80, 96);
        loadVec(sm + EH_B2, be2, 104, 128);
        loadVec(sm + EH_B3, be3, 128, 128);
        loadVec(sm + EH_U1, g_u1, 128, 128);
        loadVec(sm + EH_U2, g_u2, 128, 128);
        loadWtCol(sm, We1, 80, 32, 96, 36);
        __syncthreads();

        {
            const int bb = t0 >> 7, s0 = t0 & 127;
            const float* xsrc = x + bb * (32 * 128) + lane * 128 + s0;
            float4 a0 = *(const float4*)(xsrc);
            float4 a1 = *(const float4*)(xsrc + 4);
            ull* d = xb + lane * XS;
            ulonglong2 u0; u0.x = pk2(a0.x, a0.y); u0.y = pk2(a0.z, a0.w);
            ulonglong2 u1; u1.x = pk2(a1.x, a1.y); u1.y = pk2(a1.z, a1.w);
            *(ulonglong2*)(d) = u0;
            *(ulonglong2*)(d + 2) = u1;
        }
        __syncwarp();

        ull h1[3][4];
        mvv<32, 36, 3>(sm, xb, h1);
#pragma unroll
        for (int r = 0; r < 3; r++) {
            float bv = sm[EH_B1 + lane + 32 * r];
#pragma unroll
            for (int p = 0; p < 4; p++) {
                float a, c;
                upk2(h1[r][p], a, c);
                h1[r][p] = pk2(fmaxf(a + bv, 0.f), fmaxf(c + bv, 0.f));
            }
        }
        put2m<3>(xb, h1, 104);
        __syncthreads();
        loadWtCol(sm, We2, 104, 80, 128, 84);
        __syncthreads();

        ull h2[4][4];
        mvv<80, 84, 4>(sm, xb, h2);
#pragma unroll
        for (int r = 0; r < 4; r++) {
            float bv = sm[EH_B2 + lane + 32 * r];
#pragma unroll
            for (int p = 0; p < 4; p++) {
                float a, c;
                upk2(h2[r][p], a, c);
                h2[r][p] = pk2(fmaxf(a + bv, 0.f), fmaxf(c + bv, 0.f));
            }
        }
        put2m<4>(xb, h2, 104);
        __syncthreads();
        loadWtCol(sm, We3, 128, 104, 128, 108);
        __syncthreads();

        ull h3[4][4];
        mvv<104, 108, 4>(sm, xb, h3);
        ull d1[4] = {0ull, 0ull, 0ull, 0ull};
        ull d2[4] = {0ull, 0ull, 0ull, 0ull};
        ull* dst = g_oe2 + (size_t)grp * 512;
#pragma unroll
        for (int r = 0; r < 4; r++) {
            int k = lane + 32 * r;
            float bv = sm[EH_B3 + k];
            ull w1d = pkd(sm[EH_U1 + k]);
            ull w2d = pkd(sm[EH_U2 + k]);
            ull vP[4];
#pragma unroll
            for (int p = 0; p < 4; p++) {
                float a, c;
                upk2(h3[r][p], a, c);
                ull v = pk2(fmaxf(a + bv, 0.f), fmaxf(c + bv, 0.f));
                vP[p] = v;
                d1[p] = fma2_(w1d, v, d1[p]);
                d2[p] = fma2_(w2d, v, d2[p]);
            }
            ull* dr = dst + k * 4;
            ulonglong2 u;
            u.x = vP[0]; u.y = vP[1];
            *(ulonglong2*)(dr) = u;
            u.x = vP[2]; u.y = vP[3];
            *(ulonglong2*)(dr + 2) = u;
        }
        const float c1 = g_pre[1], c2 = g_pre[2];
        float s1v[8], s2v[8];
#pragma unroll
        for (int p = 0; p < 4; p++) {
            ull a = wsum2(d1[p]);
            upk2(a, s1v[2 * p], s1v[2 * p + 1]);
            ull c = wsum2(d2[p]);
            upk2(c, s2v[2 * p], s2v[2 * p + 1]);
        }
#pragma unroll
        for (int t = 0; t < 8; t++)
            if (lane == t) {
                g_s1[t0 + t] = s1v[t] + c1;
                g_s2[t0 + t] = s2v[t] + c2;
            }
    } else {
        loadVec(sm + EH_B1, bh1, 80, 96);
        loadVec(sm + EH_B2, bh2, 104, 128);
        loadVec(sm + EH_B3, bh3, 128, 128);
        loadWtCol(sm, Wh1, 80, 32, 96, 36);
        __syncthreads();
        if (warp == 0) expmap_smem<3>(sm + EH_B1, sm + EH_N2 + 0);
        else if (warp == 1) expmap_smem<4>(sm + EH_B2, sm + EH_N2 + 1);
        else if (warp == 2) expmap_smem<4>(sm + EH_B3, sm + EH_N2 + 2);
        __syncthreads();
        const float e1n2 = sm[EH_N2 + 0], e2n2 = sm[EH_N2 + 1], e3n2 = sm[EH_N2 + 2];

        ull xh[1][4];
        {
            const int bb = t0 >> 7, s0 = t0 & 127;
            const float* xsrc = x + bb * (32 * 128) + lane * 128 + s0;
            float4 a0 = *(const float4*)(xsrc);
            float4 a1 = *(const float4*)(xsrc + 4);
            xh[0][0] = pk2(a0.x, a0.y);
            xh[0][1] = pk2(a0.z, a0.w);
            xh[0][2] = pk2(a1.x, a1.y);
            xh[0][3] = pk2(a1.z, a1.w);
        }
        float xn2[8];
        expmap2<1>(xh, xn2);
        __syncwarp();
        put2m<1>(xb, xh, 104);
        __syncwarp();

        ull y1[3][4];
        float on2[8];
        mvv<32, 36, 3>(sm, xb, y1);
        hyplin_post<3>(sm + EH_B1, e1n2, xn2, y1, on2);
        mobrelu2<3>(y1, on2, xn2);
        put2m<3>(xb, y1, 104);
        __syncthreads();
        loadWtCol(sm, Wh2, 104, 80, 128, 84);
        __syncthreads();

        ull y2[4][4];
        mvv<80, 84, 4>(sm, xb, y2);
        hyplin_post<4>(sm + EH_B2, e2n2, xn2, y2, on2);
        mobrelu2<4>(y2, on2, xn2);
        put2m<4>(xb, y2, 104);
        __syncthreads();
        loadWtCol(sm, Wh3, 128, 104, 128, 108);
        __syncthreads();

        ull y3[4][4];
        mvv<104, 108, 4>(sm, xb, y3);
        hyplin_post<4>(sm + EH_B3, e3n2, xn2, y3, on2);
        float pf[8], nn[8];
#pragma unroll
        for (int t = 0; t < 8; t++) {
            float rn = rnorm_c(on2[t]);
            float n = fmaxf(on2[t], 1e-30f) * rn;
            float nc = fminf(n, kMaxN());
            pf[t] = rn * nc;            // ==1 (±ulp) unclamped, maxN/n clamped
            nn[t] = nc * nc;
        }
        ull pf2[4];
#pragma unroll
        for (int p = 0; p < 4; p++) pf2[p] = pk2(pf[2 * p], pf[2 * p + 1]);
        ull* dst = g_oh2 + (size_t)grp * 512;
#pragma unroll
        for (int r = 0; r < 4; r++) {
            ull* dr = dst + (lane + 32 * r) * 4;
            ulonglong2 u;
            u.x = mul2_(y3[r][0], pf2[0]);
            u.y = mul2_(y3[r][1], pf2[1]);
            *(ulonglong2*)(dr) = u;
            u.x = mul2_(y3[r][2], pf2[2]);
            u.y = mul2_(y3[r][3], pf2[3]);
            *(ulonglong2*)(dr + 2) = u;
        }
#pragma unroll
        for (int t = 0; t < 8; t++)
            if (lane == t) g_ohn2[t0 + t] = nn[t];
    }
}

// ==== Kernel 2: Wah matvec + quad reduction + scalars + pooling + classifier ==
#define K2_W   0
#define K2_EB  16896
#define K2_WTE 17024
#define K2_WTH 17152
#define K2_OS  17280
#define K2_HS  17536
#define K2_XOFF 17552
__global__ void __launch_bounds__(512) k2_kernel(
    const float* __restrict__ Wah,
    const float* __restrict__ Wte, const float* __restrict__ bte,
    const float* __restrict__ Wth, const float* __restrict__ bth,
    const float* __restrict__ Wf1, const float* __restrict__ bf1,
    const float* __restrict__ Wf2, const float* __restrict__ bf2,
    float* __restrict__ out) {
    loadWtCol(sm + K2_W, Wah, 128, 128, 128, 132);
    loadVec(sm + K2_EB, g_eb, 128, 128);
    loadVec(sm + K2_WTE, Wte, 128, 128);
    loadVec(sm + K2_WTH, Wth, 128, 128);
    __syncthreads();
    const int warp = threadIdx.x >> 5;
    const int lane = threadIdx.x & 31;
    const float ebn2 = g_pre[0];
    const float wteeb = g_pre[3], wtheb = g_pre[4];
    const float bte0 = bte[0], bth0 = bth[0];
    const int t0 = blockIdx.x * 128 + warp * 8;
    const int grp = t0 >> 3;
    ull* xb = (ull*)(sm + K2_XOFF) + warp * XBW_K2;

    // ---- stage oh to xbuf; mv = Wah . oh ----
    {
        const ull* src = g_oh2 + (size_t)grp * 512;
#pragma unroll
        for (int r = 0; r < 4; r++) {
            int k = lane + 32 * r;
            ulonglong2 u0 = *(const ulonglong2*)(src + k * 4);
            ulonglong2 u1v = *(const ulonglong2*)(src + k * 4 + 2);
            ull* d = xb + k * XS;
            *(ulonglong2*)(d) = u0;
            *(ulonglong2*)(d + 2) = u1v;
        }
    }
    float xn2[8];
#pragma unroll
    for (int t = 0; t < 8; t++) xn2[t] = g_ohn2[t0 + t];
    __syncwarp();

    ull m[4][4];
    mvv<128, 132, 4>(sm + K2_W, xb, m);

    // ---- quad reduction on raw mv ----
    float mn2[8], sme[8], smt[8], smh[8];
    {
        ull dm[4] = {0ull, 0ull, 0ull, 0ull};
        ull de[4] = {0ull, 0ull, 0ull, 0ull};
        ull dt[4] = {0ull, 0ull, 0ull, 0ull};
        ull dh[4] = {0ull, 0ull, 0ull, 0ull};
#pragma unroll
        for (int r = 0; r < 4; r++) {
            int k = lane + 32 * r;
            ull ed = pkd(sm[K2_EB + k]);
            ull td = pkd(sm[K2_WTE + k]);
            ull hd = pkd(sm[K2_WTH + k]);
#pragma unroll
            for (int p = 0; p < 4; p++) {
                dm[p] = fma2_(m[r][p], m[r][p], dm[p]);
                de[p] = fma2_(m[r][p], ed, de[p]);
                dt[p] = fma2_(m[r][p], td, dt[p]);
                dh[p] = fma2_(m[r][p], hd, dh[p]);
            }
        }
#pragma unroll
        for (int p = 0; p < 4; p++) {
            ull a = wsum2(dm[p]); upk2(a, mn2[2 * p], mn2[2 * p + 1]);
            ull c = wsum2(de[p]); upk2(c, sme[2 * p], sme[2 * p + 1]);
            ull e = wsum2(dt[p]); upk2(e, smt[2 * p], smt[2 * p + 1]);
            ull g = wsum2(dh[p]); upk2(g, smh[2 * p], smh[2 * p + 1]);
        }
    }

    // ---- per-token scalars (divide-free clamps) ----
    float w0[8], w1[8];
#pragma unroll
    for (int t = 0; t < 8; t++) {
        float rxn = rnorm_c(xn2[t]);
        float xn = fmaxf(xn2[t], 1e-30f) * rxn;
        float rmn = rnorm_c(mn2[t]);
        float mn = fmaxf(mn2[t], 1e-30f) * rmn;
        float ar = artanh_c(kSQC() * xn);
        float tth = tanh_a(mn * rxn * ar);
        float tot = rmn * kISQC() * fminf(tth, kClampT());
        float nr = fminf(tth * kISQC(), kMaxN());
        float x2 = nr * nr;
        float xy = tot * sme[t];
        float ca = 1.f + 2.f * K_C * xy + K_C * ebn2;
        float cb = 1.f - K_C * x2;
        float dn = 1.f + 2.f * K_C * xy + K_C * K_C * x2 * ebn2;
        float iv = __fdividef(1.f, fmaxf(dn, K_MIN));
        float on2 = iv * iv * (ca * ca * x2 + 2.f * ca * cb * xy + cb * cb * ebn2);
        float Af = ca * tot * iv;
        float Bf = cb * iv;
        float rn = rnorm_c(on2);
        float n = fmaxf(on2, 1e-30f) * rn;
        float nc = fminf(n, kMaxN());
        float f = artanh_c(kSQC() * nc) * rn * kISQC();   // pf*ls folded
        float s3 = f * (Af * smt[t] + Bf * wteeb);
        float s4 = f * (Af * smh[t] + Bf * wtheb);
        float aet = 0.5f * (g_s1[t0 + t] - s3) + bte0;
        float aht = 0.5f * (s4 - g_s2[t0 + t]) + bth0;
        float mx = fmaxf(aet, aht);
        float e0 = __expf(aet - mx), e1 = __expf(aht - mx);
        float inv = __fdividef(1.f, e0 + e1);
        w0[t] = e0 * inv;
        w1[t] = e1 * inv;
    }

    // ---- proc_e = w0 * out_e (stream from g_oe2), pool ----
    float acce[4];
    {
        const ull* pe = g_oe2 + (size_t)grp * 512;
        ull w0p[4];
#pragma unroll
        for (int p = 0; p < 4; p++) w0p[p] = pk2(w0[2 * p], w0[2 * p + 1]);
#pragma unroll
        for (int r = 0; r < 4; r++) {
            int k = lane + 32 * r;
            ulonglong2 u0 = *(const ulonglong2*)(pe + k * 4);
            ulonglong2 u1v = *(const ulonglong2*)(pe + k * 4 + 2);
            ull a = mul2_(w0p[0], u0.x);
            a = fma2_(w0p[1], u0.y, a);
            a = fma2_(w0p[2], u1v.x, a);
            a = fma2_(w0p[3], u1v.y, a);
            float x0, x1;
            upk2(a, x0, x1);
            acce[r] = x0 + x1;
        }
    }

    // ---- proc_h = logmap0(projx(mobius_scalar_mul(w1, out_h))), pool ----
    float acch[4];
    {
        float tt[8];
#pragma unroll
        for (int t = 0; t < 8; t++) {
            float rn = rnorm_c(xn2[t]);
            float n = fmaxf(xn2[t], 1e-30f) * rn;
            float ar = artanh_c(kSQC() * n);
            float q = tanh_a(w1[t] * ar);
            float spv = rn * kISQC() * fminf(q, kClampT());   // scv*pg folded
            float qc = fmaxf(fminf(q * kISQC(), kMaxN()), K_MIN);
            float ls = artanh_c(kSQC() * qc) * __fdividef(1.f, kSQC() * qc);
            tt[t] = spv * ls;
        }
        ull tp[4];
#pragma unroll
        for (int p = 0; p < 4; p++) tp[p] = pk2(tt[2 * p], tt[2 * p + 1]);
#pragma unroll
        for (int r = 0; r < 4; r++) {
            const ull* d = xb + (lane + 32 * r) * XS;
            ulonglong2 u0 = *(const ulonglong2*)(d);
            ulonglong2 u1v = *(const ulonglong2*)(d + 2);
            ull a = mul2_(tp[0], u0.x);
            a = fma2_(tp[1], u0.y, a);
            a = fma2_(tp[2], u1v.x, a);
            a = fma2_(tp[3], u1v.y, a);
            float x0, x1;
            upk2(a, x0, x1);
            acch[r] = x0 + x1;
        }
    }

    float* pes = sm + K2_XOFF;          // dead xbuf reuse
    float* phs = pes + 2048;
    __syncthreads();
#pragma unroll
    for (int r = 0; r < 4; r++) {
        pes[warp * 128 + lane + 32 * r] = acce[r];
        phs[warp * 128 + lane + 32 * r] = acch[r];
    }
    __syncthreads();

    float* os = sm + K2_OS;
    float* hs = sm + K2_HS;
    for (int j = threadIdx.x; j < 256; j += 512) {
        const float* src = (j < 128) ? (pes + j) : (phs + (j - 128));
        float s = 0.f;
#pragma unroll
        for (int i = 0; i < 16; i++) s += src[i * 128];
        os[j] = s * (1.0f / 128.0f);
    }
    __syncthreads();

    if (threadIdx.x < 32) {
        if (lane < 10) {
            float h = bf1[lane];
            for (int i = 0; i < 256; i++) h = fmaf(Wf1[lane * 256 + i], os[i], h);
            hs[lane] = fmaxf(h, 0.f);
        }
        __syncwarp();
        if (lane < 10) {
            float o2 = bf2[lane];
#pragma unroll
            for (int i = 0; i < 10; i++) o2 = fmaf(Wf2[lane * 10 + i], hs[i], o2);
            out[blockIdx.x * 10 + lane] = o2;
        }
    }
}

extern "C" void kernel_launch(void* const* d_in, const int* in_sizes, int n_in,
                              void* d_out, int out_size) {
    (void)in_sizes; (void)n_in; (void)out_size;
    const float* x   = (const float*)d_in[0];
    const float* We1 = (const float*)d_in[1];  const float* be1 = (const float*)d_in[2];
    const float* We2 = (const float*)d_in[3];  const float* be2 = (const float*)d_in[4];
    const float* We3 = (const float*)d_in[5];  const float* be3 = (const float*)d_in[6];
    const float* Wh1 = (const float*)d_in[7];  const float* bh1 = (const float*)d_in[8];
    const float* Wh2 = (const float*)d_in[9];  const float* bh2 = (const float*)d_in[10];
    const float* Wh3 = (const float*)d_in[11]; const float* bh3 = (const float*)d_in[12];
    const float* Wae = (const float*)d_in[13]; const float* bae = (const float*)d_in[14];
    const float* Wah = (const float*)d_in[15]; const float* bah = (const float*)d_in[16];
    const float* Wte = (const float*)d_in[17]; const float* bte = (const float*)d_in[18];
    const float* Wth = (const float*)d_in[19]; const float* bth = (const float*)d_in[20];
    const float* Wf1 = (const float*)d_in[21]; const float* bf1 = (const float*)d_in[22];
    const float* Wf2 = (const float*)d_in[23]; const float* bf2 = (const float*)d_in[24];
    float* out = (float*)d_out;

    size_t smEH = (size_t)(EH_XOFF + 16 * XBW_EH * 2) * sizeof(float);  // ~111 KB
    size_t sm2  = (size_t)(K2_XOFF + 16 * XBW_K2 * 2) * sizeof(float);  // ~136 KB

    cudaFuncSetAttribute(kEH_kernel, cudaFuncAttributeMaxDynamicSharedMemorySize, (int)smEH);
    cudaFuncSetAttribute(k2_kernel, cudaFuncAttributeMaxDynamicSharedMemorySize, (int)sm2);

    kPre_kernel<<<1, 512>>>(Wae, bae, bah, Wte, Wth);
    kEH_kernel<<<2 * NB, 512, smEH>>>(x, We1, be1, We2, be2, We3, be3,
                                      Wh1, bh1, Wh2, bh2, Wh3, bh3);
    k2_kernel<<<NB, 512, sm2>>>(Wah, Wte, bte, Wth, bth,
                                Wf1, bf1, Wf2, bf2, out);
}